// round 10
// baseline (speedup 1.0000x reference)
#include <cuda_runtime.h>
#include <cstdint>

#define B_  8
#define N_  4096
#define L_  4096
#define GC_ 32
#define IC_ 256

__device__ uint32_t g_Qb [B_*N_*16];      // [b][n][k2] bf16x2 (Q*QSCALE)
__device__ uint32_t g_Kb [B_*L_*16];      // [b][l][k2] bf16x2
__device__ float    g_VTc[B_*GC_*L_];     // [b][c][l] raw f32 (channel-major)
__device__ uint32_t g_Vb [B_*GC_*(L_/2)]; // [b][c][l2] bf16x2 of V*Dinv

#define QSCALE 0.2550668292560464f  // (1/sqrt(32)) * log2(e)

// ===========================================================================
// helpers
// ===========================================================================
__device__ __forceinline__ uint32_t smem_u32(const void* p) {
    uint32_t a;
    asm("{ .reg .u64 t; cvta.to.shared.u64 t, %1; cvt.u32.u64 %0, t; }"
        : "=r"(a) : "l"(p));
    return a;
}
__device__ __forceinline__ float ex2f(float x) {
    float y;
    asm("ex2.approx.f32 %0, %1;" : "=f"(y) : "f"(x));
    return y;
}
// FMA/ALU-only exp2 (no F2I — integer part via magic-constant rounding).
// Cubic minimax on [-0.5, 0.5], rel err ~1.1e-4.
__device__ __forceinline__ float ex2q(float x) {
    x = fmaxf(x, -80.0f);
    float t = x + 12582912.0f;            // 1.5 * 2^23 : bits(t) = 0x4B400000 + round(x)
    float i = t - 12582912.0f;
    float f = x - i;                       // f in [-0.5, 0.5]
    int   e = __float_as_int(t) << 23;     // == round(x) << 23 (low 9 bits of magic are 0)
    float p = fmaf(f, 0.0559206f, 0.2426315f);
    p = fmaf(f, p, 0.69312096f);
    p = fmaf(f, p, 0.99992486f);
    return __int_as_float(__float_as_int(p) + e);
}
__device__ __forceinline__ uint32_t pk_bf16x2(float hi, float lo) {
    uint32_t r;
    asm("cvt.rn.bf16x2.f32 %0, %1, %2;" : "=r"(r) : "f"(hi), "f"(lo));
    return r;
}
__device__ __forceinline__ void mma_bf16(float c[4], const uint32_t a[4],
                                         uint32_t b0, uint32_t b1) {
    asm volatile("mma.sync.aligned.m16n8k16.row.col.f32.bf16.bf16.f32 "
        "{%0,%1,%2,%3}, {%4,%5,%6,%7}, {%8,%9}, {%0,%1,%2,%3};"
        : "+f"(c[0]), "+f"(c[1]), "+f"(c[2]), "+f"(c[3])
        : "r"(a[0]), "r"(a[1]), "r"(a[2]), "r"(a[3]), "r"(b0), "r"(b1));
}
__device__ __forceinline__ void cp16(uint32_t s, const void* g) {
    asm volatile("cp.async.ca.shared.global [%0], [%1], 16;"
                 :: "r"(s), "l"(g) : "memory");
}
#define CP_COMMIT() asm volatile("cp.async.commit_group;" ::: "memory")
#define CP_WAIT1()  asm volatile("cp.async.wait_group 1;" ::: "memory")
#define CP_WAIT0()  asm volatile("cp.async.wait_group 0;" ::: "memory")

// ===========================================================================
// Kernel 1: Q projection (SIMT, tiny) -> packed bf16x2, QSCALE folded
// ===========================================================================
__global__ __launch_bounds__(256) void k_proj_q(
    const float* __restrict__ graph, const float* __restrict__ Wq,
    const float* __restrict__ bq)
{
    __shared__ float WqS[GC_*33];
    __shared__ float gS[64*GC_];
    int b  = blockIdx.x >> 6;
    int n0 = (blockIdx.x & 63) * 64;
    int tid = threadIdx.x;

    for (int i = tid; i < GC_*GC_; i += 256)
        WqS[(i>>5)*33 + (i&31)] = Wq[i];
    const float* gp = graph + ((long)b*N_ + n0)*GC_;
    for (int i = tid; i < 64*GC_; i += 256) gS[i] = gp[i];
    __syncthreads();

    int o2 = tid & 15, nb = tid >> 4;
    float b0 = bq[2*o2], b1 = bq[2*o2 + 1];
    #pragma unroll
    for (int j = 0; j < 4; j++) {
        int n = nb + 16*j;
        float a0 = b0, a1 = b1;
        #pragma unroll
        for (int c = 0; c < 32; c++) {
            float gv = gS[n*32 + c];
            a0 += WqS[(2*o2    )*33 + c] * gv;
            a1 += WqS[(2*o2 + 1)*33 + c] * gv;
        }
        g_Qb[((long)b*N_ + n0 + n)*16 + o2] = pk_bf16x2(a1*QSCALE, a0*QSCALE);
    }
}

// ===========================================================================
// Kernel 2: K/V projection via bf16 MMA (unchanged).
// ===========================================================================
#define PW 132
#define PI 260

__global__ __launch_bounds__(256, 1) void k_proj_kv_mma(
    const float* __restrict__ img,
    const float* __restrict__ Wk, const float* __restrict__ bk,
    const float* __restrict__ Wv, const float* __restrict__ bv)
{
    extern __shared__ uint32_t shm[];
    uint32_t* Wsm  = shm;
    float*    img0 = (float*)(shm + 64*PW);
    float*    img1 = img0 + 64*PI;

    int tid = threadIdx.x, w = tid >> 5, lane = tid & 31;
    int q = lane & 3, g = lane >> 2;
    int b = blockIdx.x >> 4, l0 = (blockIdx.x & 15) * 256;

    #pragma unroll
    for (int t = 0; t < 32; t++) {
        int u = tid + t*256;
        int o = u >> 7, c2 = u & 127;
        const float* src = (o < 32) ? (Wk + o*IC_ + 2*c2) : (Wv + (o-32)*IC_ + 2*c2);
        float2 v = *(const float2*)src;
        Wsm[o*PW + c2] = pk_bf16x2(v.y, v.x);
    }

    auto pref = [&](int ks, float* dstbuf) {
        const float* src = img + ((long)b*IC_ + ks*64)*L_ + l0;
        uint32_t dstb = smem_u32(dstbuf);
        #pragma unroll
        for (int t = 0; t < 16; t++) {
            int u = tid + t*256;
            int c = u >> 6, col = (u & 63) * 4;
            cp16(dstb + (c*PI + col)*4, src + (long)c*L_ + col);
        }
        CP_COMMIT();
    };
    pref(0, img0);

    float C[4][4][4];
    #pragma unroll
    for (int mt = 0; mt < 4; mt++) {
        const float* bias = (mt < 2) ? bk : bv;
        int ob = (mt & 1) * 16;
        float blo = bias[ob + g], bhi = bias[ob + 8 + g];
        #pragma unroll
        for (int nt = 0; nt < 4; nt++) {
            C[mt][nt][0] = C[mt][nt][1] = blo;
            C[mt][nt][2] = C[mt][nt][3] = bhi;
        }
    }
    __syncthreads();

    int lw = w * 32;
    for (int ks = 0; ks < 4; ks++) {
        if (ks < 3) { pref(ks + 1, (ks & 1) ? img0 : img1); CP_WAIT1(); }
        else CP_WAIT0();
        __syncthreads();
        const float* I = (ks & 1) ? img1 : img0;
        #pragma unroll
        for (int kk = 0; kk < 4; kk++) {
            uint32_t A[4][4];
            #pragma unroll
            for (int mt = 0; mt < 4; mt++) {
                const uint32_t* wp = Wsm + (mt*16)*PW + ks*32 + kk*8;
                A[mt][0] = wp[ g   *PW + q];
                A[mt][1] = wp[(g+8)*PW + q];
                A[mt][2] = wp[ g   *PW + q + 4];
                A[mt][3] = wp[(g+8)*PW + q + 4];
            }
            uint32_t Bf[4][2];
            #pragma unroll
            for (int nt = 0; nt < 4; nt++) {
                int l = lw + nt*8 + g;
                const float* r0 = I + (kk*16 + 2*q    )*PI + l;
                const float* r1 = I + (kk*16 + 2*q + 8)*PI + l;
                Bf[nt][0] = pk_bf16x2(r0[PI], r0[0]);
                Bf[nt][1] = pk_bf16x2(r1[PI], r1[0]);
            }
            #pragma unroll
            for (int mt = 0; mt < 4; mt++)
                #pragma unroll
                for (int nt = 0; nt < 4; nt++)
                    mma_bf16(C[mt][nt], A[mt], Bf[nt][0], Bf[nt][1]);
        }
        __syncthreads();
    }

    bool odd = (g & 1);
    int sA = 8*q + (g >> 1), sB = sA + 4;
    #pragma unroll
    for (int mt = 0; mt < 2; mt++)
        #pragma unroll
        for (int nt = 0; nt < 4; nt++) {
            float* c = C[mt][nt];
            float t0 = __shfl_sync(~0u, c[0], sA), t1 = __shfl_sync(~0u, c[1], sA);
            float t2 = __shfl_sync(~0u, c[0], sB), t3 = __shfl_sync(~0u, c[1], sB);
            float t4 = __shfl_sync(~0u, c[2], sA), t5 = __shfl_sync(~0u, c[3], sA);
            float t6 = __shfl_sync(~0u, c[2], sB), t7 = __shfl_sync(~0u, c[3], sB);
            float lo0 = odd ? t1 : t0, hi0 = odd ? t3 : t2;
            float lo1 = odd ? t5 : t4, hi1 = odd ? t7 : t6;
            long l = (long)b*L_ + l0 + lw + nt*8 + g;
            g_Kb[l*16 + mt*8 + q    ] = pk_bf16x2(hi0, lo0);
            g_Kb[l*16 + mt*8 + 4 + q] = pk_bf16x2(hi1, lo1);
        }
    #pragma unroll
    for (int mt = 2; mt < 4; mt++)
        #pragma unroll
        for (int nt = 0; nt < 4; nt++) {
            int c = (mt - 2)*16 + g;
            long base = ((long)b*GC_ + c)*L_ + l0 + lw + nt*8 + 2*q;
            *(float2*)(g_VTc + base)         = make_float2(C[mt][nt][0], C[mt][nt][1]);
            *(float2*)(g_VTc + base + 8*L_)  = make_float2(C[mt][nt][2], C[mt][nt][3]);
        }
}

// ===========================================================================
// Kernel 3: stats, 512 threads. Split exp: mt0 rows -> MUFU ex2,
// mt1 rows -> FMA/ALU poly (no F2I). Warp pair splits the n j-loop.
// ===========================================================================
#define QP 20

__global__ __launch_bounds__(512, 1) void k_stats_mma()
{
    __shared__ __align__(16) uint32_t Qs[2][128*QP];
    __shared__ float dS[2][256];
    __shared__ float dinvS[256];
    int tid = threadIdx.x, w = tid >> 5, lane = tid & 31;
    int wp = w & 7, wh = w >> 3;
    int q = lane & 3, g = lane >> 2;
    int b = blockIdx.x >> 4, l0 = (blockIdx.x & 15) * 256;
    uint32_t qs_b = smem_u32(Qs);

    uint32_t A[2][2][4];
    #pragma unroll
    for (int mt = 0; mt < 2; mt++) {
        const uint32_t* kp = g_Kb + ((long)b*L_ + l0 + wp*32 + mt*16)*16;
        #pragma unroll
        for (int kk = 0; kk < 2; kk++) {
            A[mt][kk][0] = kp[ g   *16 + 8*kk + q    ];
            A[mt][kk][1] = kp[(g+8)*16 + 8*kk + q    ];
            A[mt][kk][2] = kp[ g   *16 + 8*kk + q + 4];
            A[mt][kk][3] = kp[(g+8)*16 + 8*kk + q + 4];
        }
    }

    auto prefetch = [&](int nc, int buf) {
        const uint32_t* src = g_Qb + ((long)b*N_ + nc*128)*16;
        int r = tid >> 2, t = tid & 3;
        cp16(qs_b + (buf*128*QP + r*QP + 4*t)*4, src + r*16 + 4*t);
        CP_COMMIT();
    };
    prefetch(0, 0);

    float d[2][2] = {{0.f,0.f},{0.f,0.f}};
    int j0 = wh * 8;
    for (int nc = 0; nc < 32; nc++) {
        if (nc < 31) { prefetch(nc + 1, (nc + 1) & 1); CP_WAIT1(); }
        else CP_WAIT0();
        __syncthreads();
        const uint32_t* Q = &Qs[nc & 1][0];
        #pragma unroll 4
        for (int jj = 0; jj < 8; jj++) {
            int j = j0 + jj;
            const uint32_t* bp = &Q[(g + 8*j)*QP + q];
            uint32_t b00 = bp[0], b01 = bp[4];
            uint32_t b10 = bp[8], b11 = bp[12];
            {   // mt 0: MUFU exp
                float c[4] = {0.f, 0.f, 0.f, 0.f};
                mma_bf16(c, A[0][0], b00, b01);
                mma_bf16(c, A[0][1], b10, b11);
                d[0][0] += ex2f(c[0]) + ex2f(c[1]);
                d[0][1] += ex2f(c[2]) + ex2f(c[3]);
            }
            {   // mt 1: FMA/ALU poly exp (no F2I)
                float c[4] = {0.f, 0.f, 0.f, 0.f};
                mma_bf16(c, A[1][0], b00, b01);
                mma_bf16(c, A[1][1], b10, b11);
                d[1][0] += ex2q(c[0]) + ex2q(c[1]);
                d[1][1] += ex2q(c[2]) + ex2q(c[3]);
            }
        }
        __syncthreads();
    }
    #pragma unroll
    for (int mt = 0; mt < 2; mt++) {
        #pragma unroll
        for (int h = 0; h < 2; h++) {
            float dv = d[mt][h];
            dv += __shfl_xor_sync(~0u, dv, 1);
            dv += __shfl_xor_sync(~0u, dv, 2);
            if (q == 0) dS[wh][wp*32 + mt*16 + h*8 + g] = dv;
        }
    }
    __syncthreads();
    if (tid < 256) dinvS[tid] = 1.0f / (dS[0][tid] + dS[1][tid]);
    __syncthreads();

    uint32_t* dst = g_Vb + ((long)b*GC_)*(L_/2) + (l0 >> 1);
    const float* vsrc = g_VTc + ((long)b*GC_)*L_ + l0;
    #pragma unroll
    for (int t = 0; t < 8; t++) {
        int u = tid + t*512;
        int c = u >> 7, l2 = u & 127;
        float2 v = *(const float2*)(vsrc + (long)c*L_ + 2*l2);
        dst[(long)c*(L_/2) + l2] =
            pk_bf16x2(v.y * dinvS[2*l2 + 1], v.x * dinvS[2*l2]);
    }
}

// ===========================================================================
// Kernel 4: final, 512 threads, pure MUFU exp (unchanged from R9).
// ===========================================================================
#define KP 20
#define VP 68
#define SH_WORDS (2*128*KP + 2*32*VP)

__global__ __launch_bounds__(512, 1) void k_final_mma(
    const float* __restrict__ graph, const float* __restrict__ Wc,
    const float* __restrict__ bc, float* __restrict__ out)
{
    __shared__ __align__(16) uint32_t SH[SH_WORDS];
    __shared__ uint32_t Wb[32*17];
    int tid = threadIdx.x, w = tid >> 5, lane = tid & 31;
    int wp = w & 7, wh = w >> 3;
    int q = lane & 3, g = lane >> 2;
    int b = blockIdx.x >> 4, n0 = (blockIdx.x & 15) * 256;
    uint32_t sh_b = smem_u32(SH);
    uint32_t vb_off = 2*128*KP;

    uint32_t A[2][2][4];
    #pragma unroll
    for (int mt = 0; mt < 2; mt++) {
        const uint32_t* qp = g_Qb + ((long)b*N_ + n0 + wp*32 + mt*16)*16;
        #pragma unroll
        for (int kk = 0; kk < 2; kk++) {
            A[mt][kk][0] = qp[ g   *16 + 8*kk + q    ];
            A[mt][kk][1] = qp[(g+8)*16 + 8*kk + q    ];
            A[mt][kk][2] = qp[ g   *16 + 8*kk + q + 4];
            A[mt][kk][3] = qp[(g+8)*16 + 8*kk + q + 4];
        }
    }
    for (int i = tid; i < 32*16; i += 512) {
        int o = i >> 4, c2 = i & 15;
        Wb[o*17 + c2] = pk_bf16x2(Wc[o*32 + 2*c2 + 1], Wc[o*32 + 2*c2]);
    }

    const uint32_t* vbsrc = g_Vb + ((long)b*GC_)*(L_/2);
    auto prefetch = [&](int lc, int buf) {
        const uint32_t* ksrc = g_Kb + ((long)b*L_ + lc*128)*16;
        {
            int r = tid >> 2, t = tid & 3;
            cp16(sh_b + (buf*128*KP + r*KP + 4*t)*4, ksrc + r*16 + 4*t);
        }
        {
            int c = tid >> 4, t2 = tid & 15;
            cp16(sh_b + (vb_off + buf*32*VP + c*VP + 4*t2)*4,
                 vbsrc + (long)c*(L_/2) + lc*64 + 4*t2);
        }
        CP_COMMIT();
    };
    prefetch(0, 0);

    float mc[2][4][4];
    #pragma unroll
    for (int mt = 0; mt < 2; mt++)
        #pragma unroll
        for (int cf = 0; cf < 4; cf++)
            #pragma unroll
            for (int x = 0; x < 4; x++) mc[mt][cf][x] = 0.f;

    int s0 = wh * 4;
    for (int lc = 0; lc < 32; lc++) {
        if (lc < 31) { prefetch(lc + 1, (lc + 1) & 1); CP_WAIT1(); }
        else CP_WAIT0();
        __syncthreads();
        const uint32_t* K = SH + (lc & 1)*128*KP;
        const uint32_t* V = SH + vb_off + (lc & 1)*32*VP;

        #pragma unroll 2
        for (int ss = 0; ss < 4; ss++) {
            int s = s0 + ss;
            const uint32_t* bpa = &K[(g + 16*s    )*KP + q];
            const uint32_t* bpb = &K[(g + 16*s + 8)*KP + q];
            uint32_t ba00 = bpa[0], ba01 = bpa[4], ba10 = bpa[8], ba11 = bpa[12];
            uint32_t bb00 = bpb[0], bb01 = bpb[4], bb10 = bpb[8], bb11 = bpb[12];
            uint32_t vb0[4], vb1[4];
            #pragma unroll
            for (int cf = 0; cf < 4; cf++) {
                vb0[cf] = V[(g + 8*cf)*VP + 8*s + q    ];
                vb1[cf] = V[(g + 8*cf)*VP + 8*s + q + 4];
            }
            #pragma unroll
            for (int mt = 0; mt < 2; mt++) {
                float c0[4] = {0.f,0.f,0.f,0.f};
                float c1[4] = {0.f,0.f,0.f,0.f};
                mma_bf16(c0, A[mt][0], ba00, ba01);
                mma_bf16(c0, A[mt][1], ba10, ba11);
                mma_bf16(c1, A[mt][0], bb00, bb01);
                mma_bf16(c1, A[mt][1], bb10, bb11);
                uint32_t A2[4];
                A2[0] = pk_bf16x2(ex2f(c0[1]), ex2f(c0[0]));
                A2[1] = pk_bf16x2(ex2f(c0[3]), ex2f(c0[2]));
                A2[2] = pk_bf16x2(ex2f(c1[1]), ex2f(c1[0]));
                A2[3] = pk_bf16x2(ex2f(c1[3]), ex2f(c1[2]));
                #pragma unroll
                for (int cf = 0; cf < 4; cf++)
                    mma_bf16(mc[mt][cf], A2, vb0[cf], vb1[cf]);
            }
        }
        __syncthreads();
    }

    // combine warp-pair partials via smem (reuse SH as msgP[256][36])
    float* msgP = (float*)SH;
    if (wh == 1) {
        #pragma unroll
        for (int mt = 0; mt < 2; mt++) {
            int rb = wp*32 + mt*16;
            #pragma unroll
            for (int cf = 0; cf < 4; cf++) {
                int col = cf*8 + 2*q;
                *(float2*)&msgP[(rb + g    )*36 + col] =
                    make_float2(mc[mt][cf][0], mc[mt][cf][1]);
                *(float2*)&msgP[(rb + g + 8)*36 + col] =
                    make_float2(mc[mt][cf][2], mc[mt][cf][3]);
            }
        }
    }
    __syncthreads();

    if (wh == 0) {
        #pragma unroll
        for (int mt = 0; mt < 2; mt++) {
            int rb = wp*32 + mt*16;
            #pragma unroll
            for (int cf = 0; cf < 4; cf++) {
                int col = cf*8 + 2*q;
                float2 p0 = *(const float2*)&msgP[(rb + g    )*36 + col];
                float2 p1 = *(const float2*)&msgP[(rb + g + 8)*36 + col];
                mc[mt][cf][0] += p0.x; mc[mt][cf][1] += p0.y;
                mc[mt][cf][2] += p1.x; mc[mt][cf][3] += p1.y;
            }
        }
        #pragma unroll
        for (int mt = 0; mt < 2; mt++) {
            uint32_t A3[2][4];
            #pragma unroll
            for (int t = 0; t < 2; t++) {
                A3[t][0] = pk_bf16x2(mc[mt][2*t  ][1], mc[mt][2*t  ][0]);
                A3[t][1] = pk_bf16x2(mc[mt][2*t  ][3], mc[mt][2*t  ][2]);
                A3[t][2] = pk_bf16x2(mc[mt][2*t+1][1], mc[mt][2*t+1][0]);
                A3[t][3] = pk_bf16x2(mc[mt][2*t+1][3], mc[mt][2*t+1][2]);
            }
            long nbase = (long)b*N_ + n0 + wp*32 + mt*16;
            const float* gp = graph + nbase*32;
            float* op = out + nbase*32;
            #pragma unroll
            for (int of = 0; of < 4; of++) {
                int col = 8*of + 2*q;
                float bc0 = bc[col], bc1 = bc[col + 1];
                float2 gr0 = *(const float2*)(gp + g*32 + col);
                float2 gr1 = *(const float2*)(gp + (g + 8)*32 + col);
                float c[4] = { gr0.x + bc0, gr0.y + bc1, gr1.x + bc0, gr1.y + bc1 };
                #pragma unroll
                for (int t = 0; t < 2; t++) {
                    uint32_t b0 = Wb[(g + 8*of)*17 + 8*t + q    ];
                    uint32_t b1 = Wb[(g + 8*of)*17 + 8*t + q + 4];
                    mma_bf16(c, A3[t], b0, b1);
                }
                *(float2*)(op + g*32 + col)       = make_float2(c[0], c[1]);
                *(float2*)(op + (g + 8)*32 + col) = make_float2(c[2], c[3]);
            }
        }
    }
}

// ===========================================================================
extern "C" void kernel_launch(void* const* d_in, const int* in_sizes, int n_in,
                              void* d_out, int out_size)
{
    const float* graph = (const float*)d_in[0];
    const float* img   = (const float*)d_in[1];
    const float* Wq    = (const float*)d_in[2];
    const float* bq    = (const float*)d_in[3];
    const float* Wk    = (const float*)d_in[4];
    const float* bk    = (const float*)d_in[5];
    const float* Wv    = (const float*)d_in[6];
    const float* bv    = (const float*)d_in[7];
    const float* Wc    = (const float*)d_in[8];
    const float* bc    = (const float*)d_in[9];
    float* out = (float*)d_out;

    size_t proj_smem = (64*PW + 2*64*PI) * sizeof(uint32_t);
    static int attr_set = 0;
    if (!attr_set) {
        cudaFuncSetAttribute(k_proj_kv_mma,
                             cudaFuncAttributeMaxDynamicSharedMemorySize,
                             (int)proj_smem);
        attr_set = 1;
    }

    k_proj_q     <<<B_*(N_/64), 256>>>(graph, Wq, bq);
    k_proj_kv_mma<<<B_*(L_/256), 256, proj_smem>>>(img, Wk, bk, Wv, bv);
    k_stats_mma  <<<B_*(L_/256), 512>>>();
    k_final_mma  <<<B_*(N_/256), 512>>>(graph, Wc, bc, out);
}

// round 11
// speedup vs baseline: 1.2055x; 1.2055x over previous
#include <cuda_runtime.h>
#include <cstdint>

#define B_  8
#define N_  4096
#define L_  4096
#define GC_ 32
#define IC_ 256

__device__ uint32_t g_Qb [B_*N_*16];      // [b][n][k2] f16x2 (Q*QSCALE)
__device__ uint32_t g_Kb [B_*L_*16];      // [b][l][k2] f16x2
__device__ float    g_VTc[B_*GC_*L_];     // [b][c][l] raw f32 (channel-major)
__device__ uint32_t g_Vb [B_*GC_*(L_/2)]; // [b][c][l2] f16x2 of V*Dinv

#define QSCALE 0.2550668292560464f  // (1/sqrt(32)) * log2(e)

// ===========================================================================
// helpers
// ===========================================================================
__device__ __forceinline__ uint32_t smem_u32(const void* p) {
    uint32_t a;
    asm("{ .reg .u64 t; cvta.to.shared.u64 t, %1; cvt.u32.u64 %0, t; }"
        : "=r"(a) : "l"(p));
    return a;
}
// pack two f32 -> f16x2 (F2FP, alu pipe)
__device__ __forceinline__ uint32_t pk_h2(float hi, float lo) {
    uint32_t r;
    asm("cvt.rn.f16x2.f32 %0, %1, %2;" : "=r"(r) : "f"(hi), "f"(lo));
    return r;
}
// two exps in one MUFU op
__device__ __forceinline__ uint32_t ex2h2(uint32_t x) {
    uint32_t y;
    asm("ex2.approx.f16x2 %0, %1;" : "=r"(y) : "r"(x));
    return y;
}
__device__ __forceinline__ uint32_t hadd2(uint32_t a, uint32_t b) {
    uint32_t r;
    asm("add.rn.f16x2 %0, %1, %2;" : "=r"(r) : "r"(a), "r"(b));
    return r;
}
__device__ __forceinline__ float hsum2f(uint32_t h2) {
    float lo, hi;
    asm("{ .reg .b16 l, h;\n\t mov.b32 {l, h}, %2;\n\t"
        "cvt.f32.f16 %0, l;\n\t cvt.f32.f16 %1, h; }"
        : "=f"(lo), "=f"(hi) : "r"(h2));
    return lo + hi;
}
__device__ __forceinline__ void mma_f16(float c[4], const uint32_t a[4],
                                        uint32_t b0, uint32_t b1) {
    asm volatile("mma.sync.aligned.m16n8k16.row.col.f32.f16.f16.f32 "
        "{%0,%1,%2,%3}, {%4,%5,%6,%7}, {%8,%9}, {%0,%1,%2,%3};"
        : "+f"(c[0]), "+f"(c[1]), "+f"(c[2]), "+f"(c[3])
        : "r"(a[0]), "r"(a[1]), "r"(a[2]), "r"(a[3]), "r"(b0), "r"(b1));
}
__device__ __forceinline__ void cp16(uint32_t s, const void* g) {
    asm volatile("cp.async.ca.shared.global [%0], [%1], 16;"
                 :: "r"(s), "l"(g) : "memory");
}
#define CP_COMMIT() asm volatile("cp.async.commit_group;" ::: "memory")
#define CP_WAIT1()  asm volatile("cp.async.wait_group 1;" ::: "memory")
#define CP_WAIT0()  asm volatile("cp.async.wait_group 0;" ::: "memory")

// ===========================================================================
// Kernel 1: Q projection (SIMT, tiny) -> packed f16x2, QSCALE folded
// ===========================================================================
__global__ __launch_bounds__(256) void k_proj_q(
    const float* __restrict__ graph, const float* __restrict__ Wq,
    const float* __restrict__ bq)
{
    __shared__ float WqS[GC_*33];
    __shared__ float gS[64*GC_];
    int b  = blockIdx.x >> 6;
    int n0 = (blockIdx.x & 63) * 64;
    int tid = threadIdx.x;

    for (int i = tid; i < GC_*GC_; i += 256)
        WqS[(i>>5)*33 + (i&31)] = Wq[i];
    const float* gp = graph + ((long)b*N_ + n0)*GC_;
    for (int i = tid; i < 64*GC_; i += 256) gS[i] = gp[i];
    __syncthreads();

    int o2 = tid & 15, nb = tid >> 4;
    float b0 = bq[2*o2], b1 = bq[2*o2 + 1];
    #pragma unroll
    for (int j = 0; j < 4; j++) {
        int n = nb + 16*j;
        float a0 = b0, a1 = b1;
        #pragma unroll
        for (int c = 0; c < 32; c++) {
            float gv = gS[n*32 + c];
            a0 += WqS[(2*o2    )*33 + c] * gv;
            a1 += WqS[(2*o2 + 1)*33 + c] * gv;
        }
        g_Qb[((long)b*N_ + n0 + n)*16 + o2] = pk_h2(a1*QSCALE, a0*QSCALE);
    }
}

// ===========================================================================
// Kernel 2: K/V projection via f16 MMA.
// ===========================================================================
#define PW 132
#define PI 260

__global__ __launch_bounds__(256, 1) void k_proj_kv_mma(
    const float* __restrict__ img,
    const float* __restrict__ Wk, const float* __restrict__ bk,
    const float* __restrict__ Wv, const float* __restrict__ bv)
{
    extern __shared__ uint32_t shm[];
    uint32_t* Wsm  = shm;
    float*    img0 = (float*)(shm + 64*PW);
    float*    img1 = img0 + 64*PI;

    int tid = threadIdx.x, w = tid >> 5, lane = tid & 31;
    int q = lane & 3, g = lane >> 2;
    int b = blockIdx.x >> 4, l0 = (blockIdx.x & 15) * 256;

    #pragma unroll
    for (int t = 0; t < 32; t++) {
        int u = tid + t*256;
        int o = u >> 7, c2 = u & 127;
        const float* src = (o < 32) ? (Wk + o*IC_ + 2*c2) : (Wv + (o-32)*IC_ + 2*c2);
        float2 v = *(const float2*)src;
        Wsm[o*PW + c2] = pk_h2(v.y, v.x);
    }

    auto pref = [&](int ks, float* dstbuf) {
        const float* src = img + ((long)b*IC_ + ks*64)*L_ + l0;
        uint32_t dstb = smem_u32(dstbuf);
        #pragma unroll
        for (int t = 0; t < 16; t++) {
            int u = tid + t*256;
            int c = u >> 6, col = (u & 63) * 4;
            cp16(dstb + (c*PI + col)*4, src + (long)c*L_ + col);
        }
        CP_COMMIT();
    };
    pref(0, img0);

    float C[4][4][4];
    #pragma unroll
    for (int mt = 0; mt < 4; mt++) {
        const float* bias = (mt < 2) ? bk : bv;
        int ob = (mt & 1) * 16;
        float blo = bias[ob + g], bhi = bias[ob + 8 + g];
        #pragma unroll
        for (int nt = 0; nt < 4; nt++) {
            C[mt][nt][0] = C[mt][nt][1] = blo;
            C[mt][nt][2] = C[mt][nt][3] = bhi;
        }
    }
    __syncthreads();

    int lw = w * 32;
    for (int ks = 0; ks < 4; ks++) {
        if (ks < 3) { pref(ks + 1, (ks & 1) ? img0 : img1); CP_WAIT1(); }
        else CP_WAIT0();
        __syncthreads();
        const float* I = (ks & 1) ? img1 : img0;
        #pragma unroll
        for (int kk = 0; kk < 4; kk++) {
            uint32_t A[4][4];
            #pragma unroll
            for (int mt = 0; mt < 4; mt++) {
                const uint32_t* wp = Wsm + (mt*16)*PW + ks*32 + kk*8;
                A[mt][0] = wp[ g   *PW + q];
                A[mt][1] = wp[(g+8)*PW + q];
                A[mt][2] = wp[ g   *PW + q + 4];
                A[mt][3] = wp[(g+8)*PW + q + 4];
            }
            uint32_t Bf[4][2];
            #pragma unroll
            for (int nt = 0; nt < 4; nt++) {
                int l = lw + nt*8 + g;
                const float* r0 = I + (kk*16 + 2*q    )*PI + l;
                const float* r1 = I + (kk*16 + 2*q + 8)*PI + l;
                Bf[nt][0] = pk_h2(r0[PI], r0[0]);
                Bf[nt][1] = pk_h2(r1[PI], r1[0]);
            }
            #pragma unroll
            for (int mt = 0; mt < 4; mt++)
                #pragma unroll
                for (int nt = 0; nt < 4; nt++)
                    mma_f16(C[mt][nt], A[mt], Bf[nt][0], Bf[nt][1]);
        }
        __syncthreads();
    }

    bool odd = (g & 1);
    int sA = 8*q + (g >> 1), sB = sA + 4;
    #pragma unroll
    for (int mt = 0; mt < 2; mt++)
        #pragma unroll
        for (int nt = 0; nt < 4; nt++) {
            float* c = C[mt][nt];
            float t0 = __shfl_sync(~0u, c[0], sA), t1 = __shfl_sync(~0u, c[1], sA);
            float t2 = __shfl_sync(~0u, c[0], sB), t3 = __shfl_sync(~0u, c[1], sB);
            float t4 = __shfl_sync(~0u, c[2], sA), t5 = __shfl_sync(~0u, c[3], sA);
            float t6 = __shfl_sync(~0u, c[2], sB), t7 = __shfl_sync(~0u, c[3], sB);
            float lo0 = odd ? t1 : t0, hi0 = odd ? t3 : t2;
            float lo1 = odd ? t5 : t4, hi1 = odd ? t7 : t6;
            long l = (long)b*L_ + l0 + lw + nt*8 + g;
            g_Kb[l*16 + mt*8 + q    ] = pk_h2(hi0, lo0);
            g_Kb[l*16 + mt*8 + 4 + q] = pk_h2(hi1, lo1);
        }
    #pragma unroll
    for (int mt = 2; mt < 4; mt++)
        #pragma unroll
        for (int nt = 0; nt < 4; nt++) {
            int c = (mt - 2)*16 + g;
            long base = ((long)b*GC_ + c)*L_ + l0 + lw + nt*8 + 2*q;
            *(float2*)(g_VTc + base)         = make_float2(C[mt][nt][0], C[mt][nt][1]);
            *(float2*)(g_VTc + base + 8*L_)  = make_float2(C[mt][nt][2], C[mt][nt][3]);
        }
}

// ===========================================================================
// Kernel 3: stats, 512 threads. f16x2 exp (2 exps / MUFU op), f16x2 partial
// sums flushed to f32 per n-chunk. Warp pair splits the n j-loop.
// ===========================================================================
#define QP 20

__global__ __launch_bounds__(512, 1) void k_stats_mma()
{
    __shared__ __align__(16) uint32_t Qs[2][128*QP];
    __shared__ float dS[2][256];
    __shared__ float dinvS[256];
    int tid = threadIdx.x, w = tid >> 5, lane = tid & 31;
    int wp = w & 7, wh = w >> 3;
    int q = lane & 3, g = lane >> 2;
    int b = blockIdx.x >> 4, l0 = (blockIdx.x & 15) * 256;
    uint32_t qs_b = smem_u32(Qs);

    uint32_t A[2][2][4];
    #pragma unroll
    for (int mt = 0; mt < 2; mt++) {
        const uint32_t* kp = g_Kb + ((long)b*L_ + l0 + wp*32 + mt*16)*16;
        #pragma unroll
        for (int kk = 0; kk < 2; kk++) {
            A[mt][kk][0] = kp[ g   *16 + 8*kk + q    ];
            A[mt][kk][1] = kp[(g+8)*16 + 8*kk + q    ];
            A[mt][kk][2] = kp[ g   *16 + 8*kk + q + 4];
            A[mt][kk][3] = kp[(g+8)*16 + 8*kk + q + 4];
        }
    }

    auto prefetch = [&](int nc, int buf) {
        const uint32_t* src = g_Qb + ((long)b*N_ + nc*128)*16;
        int r = tid >> 2, t = tid & 3;
        cp16(qs_b + (buf*128*QP + r*QP + 4*t)*4, src + r*16 + 4*t);
        CP_COMMIT();
    };
    prefetch(0, 0);

    float d[2][2] = {{0.f,0.f},{0.f,0.f}};
    int j0 = wh * 8;
    for (int nc = 0; nc < 32; nc++) {
        if (nc < 31) { prefetch(nc + 1, (nc + 1) & 1); CP_WAIT1(); }
        else CP_WAIT0();
        __syncthreads();
        const uint32_t* Q = &Qs[nc & 1][0];
        uint32_t dh[2][2] = {{0u,0u},{0u,0u}};
        #pragma unroll 4
        for (int jj = 0; jj < 8; jj++) {
            int j = j0 + jj;
            const uint32_t* bp = &Q[(g + 8*j)*QP + q];
            uint32_t b00 = bp[0], b01 = bp[4];
            uint32_t b10 = bp[8], b11 = bp[12];
            #pragma unroll
            for (int mt = 0; mt < 2; mt++) {
                float c[4] = {0.f, 0.f, 0.f, 0.f};
                mma_f16(c, A[mt][0], b00, b01);
                mma_f16(c, A[mt][1], b10, b11);
                dh[mt][0] = hadd2(dh[mt][0], ex2h2(pk_h2(c[1], c[0])));
                dh[mt][1] = hadd2(dh[mt][1], ex2h2(pk_h2(c[3], c[2])));
            }
        }
        #pragma unroll
        for (int mt = 0; mt < 2; mt++) {
            d[mt][0] += hsum2f(dh[mt][0]);
            d[mt][1] += hsum2f(dh[mt][1]);
        }
        __syncthreads();
    }
    #pragma unroll
    for (int mt = 0; mt < 2; mt++) {
        #pragma unroll
        for (int h = 0; h < 2; h++) {
            float dv = d[mt][h];
            dv += __shfl_xor_sync(~0u, dv, 1);
            dv += __shfl_xor_sync(~0u, dv, 2);
            if (q == 0) dS[wh][wp*32 + mt*16 + h*8 + g] = dv;
        }
    }
    __syncthreads();
    if (tid < 256) dinvS[tid] = 1.0f / (dS[0][tid] + dS[1][tid]);
    __syncthreads();

    uint32_t* dst = g_Vb + ((long)b*GC_)*(L_/2) + (l0 >> 1);
    const float* vsrc = g_VTc + ((long)b*GC_)*L_ + l0;
    #pragma unroll
    for (int t = 0; t < 8; t++) {
        int u = tid + t*512;
        int c = u >> 7, l2 = u & 127;
        float2 v = *(const float2*)(vsrc + (long)c*L_ + 2*l2);
        dst[(long)c*(L_/2) + l2] =
            pk_h2(v.y * dinvS[2*l2 + 1], v.x * dinvS[2*l2]);
    }
}

// ===========================================================================
// Kernel 4: final, 512 threads. f16 MMAs; exp via pack(alu) + ex2.f16x2 —
// exp output register IS the GEMM2 A-fragment.
// ===========================================================================
#define KP 20
#define VP 68
#define SH_WORDS (2*128*KP + 2*32*VP)

__global__ __launch_bounds__(512, 1) void k_final_mma(
    const float* __restrict__ graph, const float* __restrict__ Wc,
    const float* __restrict__ bc, float* __restrict__ out)
{
    __shared__ __align__(16) uint32_t SH[SH_WORDS];
    __shared__ uint32_t Wb[32*17];
    int tid = threadIdx.x, w = tid >> 5, lane = tid & 31;
    int wp = w & 7, wh = w >> 3;
    int q = lane & 3, g = lane >> 2;
    int b = blockIdx.x >> 4, n0 = (blockIdx.x & 15) * 256;
    uint32_t sh_b = smem_u32(SH);
    uint32_t vb_off = 2*128*KP;

    uint32_t A[2][2][4];
    #pragma unroll
    for (int mt = 0; mt < 2; mt++) {
        const uint32_t* qp = g_Qb + ((long)b*N_ + n0 + wp*32 + mt*16)*16;
        #pragma unroll
        for (int kk = 0; kk < 2; kk++) {
            A[mt][kk][0] = qp[ g   *16 + 8*kk + q    ];
            A[mt][kk][1] = qp[(g+8)*16 + 8*kk + q    ];
            A[mt][kk][2] = qp[ g   *16 + 8*kk + q + 4];
            A[mt][kk][3] = qp[(g+8)*16 + 8*kk + q + 4];
        }
    }
    for (int i = tid; i < 32*16; i += 512) {
        int o = i >> 4, c2 = i & 15;
        Wb[o*17 + c2] = pk_h2(Wc[o*32 + 2*c2 + 1], Wc[o*32 + 2*c2]);
    }

    const uint32_t* vbsrc = g_Vb + ((long)b*GC_)*(L_/2);
    auto prefetch = [&](int lc, int buf) {
        const uint32_t* ksrc = g_Kb + ((long)b*L_ + lc*128)*16;
        {
            int r = tid >> 2, t = tid & 3;
            cp16(sh_b + (buf*128*KP + r*KP + 4*t)*4, ksrc + r*16 + 4*t);
        }
        {
            int c = tid >> 4, t2 = tid & 15;
            cp16(sh_b + (vb_off + buf*32*VP + c*VP + 4*t2)*4,
                 vbsrc + (long)c*(L_/2) + lc*64 + 4*t2);
        }
        CP_COMMIT();
    };
    prefetch(0, 0);

    float mc[2][4][4];
    #pragma unroll
    for (int mt = 0; mt < 2; mt++)
        #pragma unroll
        for (int cf = 0; cf < 4; cf++)
            #pragma unroll
            for (int x = 0; x < 4; x++) mc[mt][cf][x] = 0.f;

    int s0 = wh * 4;
    for (int lc = 0; lc < 32; lc++) {
        if (lc < 31) { prefetch(lc + 1, (lc + 1) & 1); CP_WAIT1(); }
        else CP_WAIT0();
        __syncthreads();
        const uint32_t* K = SH + (lc & 1)*128*KP;
        const uint32_t* V = SH + vb_off + (lc & 1)*32*VP;

        #pragma unroll 2
        for (int ss = 0; ss < 4; ss++) {
            int s = s0 + ss;
            const uint32_t* bpa = &K[(g + 16*s    )*KP + q];
            const uint32_t* bpb = &K[(g + 16*s + 8)*KP + q];
            uint32_t ba00 = bpa[0], ba01 = bpa[4], ba10 = bpa[8], ba11 = bpa[12];
            uint32_t bb00 = bpb[0], bb01 = bpb[4], bb10 = bpb[8], bb11 = bpb[12];
            uint32_t vb0[4], vb1[4];
            #pragma unroll
            for (int cf = 0; cf < 4; cf++) {
                vb0[cf] = V[(g + 8*cf)*VP + 8*s + q    ];
                vb1[cf] = V[(g + 8*cf)*VP + 8*s + q + 4];
            }
            #pragma unroll
            for (int mt = 0; mt < 2; mt++) {
                float c0[4] = {0.f,0.f,0.f,0.f};
                float c1[4] = {0.f,0.f,0.f,0.f};
                mma_f16(c0, A[mt][0], ba00, ba01);
                mma_f16(c0, A[mt][1], ba10, ba11);
                mma_f16(c1, A[mt][0], bb00, bb01);
                mma_f16(c1, A[mt][1], bb10, bb11);
                uint32_t A2[4];
                A2[0] = ex2h2(pk_h2(c0[1], c0[0]));
                A2[1] = ex2h2(pk_h2(c0[3], c0[2]));
                A2[2] = ex2h2(pk_h2(c1[1], c1[0]));
                A2[3] = ex2h2(pk_h2(c1[3], c1[2]));
                #pragma unroll
                for (int cf = 0; cf < 4; cf++)
                    mma_f16(mc[mt][cf], A2, vb0[cf], vb1[cf]);
            }
        }
        __syncthreads();
    }

    // combine warp-pair partials via smem (reuse SH as msgP[256][36])
    float* msgP = (float*)SH;
    if (wh == 1) {
        #pragma unroll
        for (int mt = 0; mt < 2; mt++) {
            int rb = wp*32 + mt*16;
            #pragma unroll
            for (int cf = 0; cf < 4; cf++) {
                int col = cf*8 + 2*q;
                *(float2*)&msgP[(rb + g    )*36 + col] =
                    make_float2(mc[mt][cf][0], mc[mt][cf][1]);
                *(float2*)&msgP[(rb + g + 8)*36 + col] =
                    make_float2(mc[mt][cf][2], mc[mt][cf][3]);
            }
        }
    }
    __syncthreads();

    if (wh == 0) {
        #pragma unroll
        for (int mt = 0; mt < 2; mt++) {
            int rb = wp*32 + mt*16;
            #pragma unroll
            for (int cf = 0; cf < 4; cf++) {
                int col = cf*8 + 2*q;
                float2 p0 = *(const float2*)&msgP[(rb + g    )*36 + col];
                float2 p1 = *(const float2*)&msgP[(rb + g + 8)*36 + col];
                mc[mt][cf][0] += p0.x; mc[mt][cf][1] += p0.y;
                mc[mt][cf][2] += p1.x; mc[mt][cf][3] += p1.y;
            }
        }
        #pragma unroll
        for (int mt = 0; mt < 2; mt++) {
            uint32_t A3[2][4];
            #pragma unroll
            for (int t = 0; t < 2; t++) {
                A3[t][0] = pk_h2(mc[mt][2*t  ][1], mc[mt][2*t  ][0]);
                A3[t][1] = pk_h2(mc[mt][2*t  ][3], mc[mt][2*t  ][2]);
                A3[t][2] = pk_h2(mc[mt][2*t+1][1], mc[mt][2*t+1][0]);
                A3[t][3] = pk_h2(mc[mt][2*t+1][3], mc[mt][2*t+1][2]);
            }
            long nbase = (long)b*N_ + n0 + wp*32 + mt*16;
            const float* gp = graph + nbase*32;
            float* op = out + nbase*32;
            #pragma unroll
            for (int of = 0; of < 4; of++) {
                int col = 8*of + 2*q;
                float bc0 = bc[col], bc1 = bc[col + 1];
                float2 gr0 = *(const float2*)(gp + g*32 + col);
                float2 gr1 = *(const float2*)(gp + (g + 8)*32 + col);
                float c[4] = { gr0.x + bc0, gr0.y + bc1, gr1.x + bc0, gr1.y + bc1 };
                #pragma unroll
                for (int t = 0; t < 2; t++) {
                    uint32_t b0 = Wb[(g + 8*of)*17 + 8*t + q    ];
                    uint32_t b1 = Wb[(g + 8*of)*17 + 8*t + q + 4];
                    mma_f16(c, A3[t], b0, b1);
                }
                *(float2*)(op + g*32 + col)       = make_float2(c[0], c[1]);
                *(float2*)(op + (g + 8)*32 + col) = make_float2(c[2], c[3]);
            }
        }
    }
}

// ===========================================================================
extern "C" void kernel_launch(void* const* d_in, const int* in_sizes, int n_in,
                              void* d_out, int out_size)
{
    const float* graph = (const float*)d_in[0];
    const float* img   = (const float*)d_in[1];
    const float* Wq    = (const float*)d_in[2];
    const float* bq    = (const float*)d_in[3];
    const float* Wk    = (const float*)d_in[4];
    const float* bk    = (const float*)d_in[5];
    const float* Wv    = (const float*)d_in[6];
    const float* bv    = (const float*)d_in[7];
    const float* Wc    = (const float*)d_in[8];
    const float* bc    = (const float*)d_in[9];
    float* out = (float*)d_out;

    size_t proj_smem = (64*PW + 2*64*PI) * sizeof(uint32_t);
    static int attr_set = 0;
    if (!attr_set) {
        cudaFuncSetAttribute(k_proj_kv_mma,
                             cudaFuncAttributeMaxDynamicSharedMemorySize,
                             (int)proj_smem);
        attr_set = 1;
    }

    k_proj_q     <<<B_*(N_/64), 256>>>(graph, Wq, bq);
    k_proj_kv_mma<<<B_*(L_/256), 256, proj_smem>>>(img, Wk, bk, Wv, bv);
    k_stats_mma  <<<B_*(L_/256), 512>>>();
    k_final_mma  <<<B_*(N_/256), 512>>>(graph, Wc, bc, out);
}

// round 13
// speedup vs baseline: 1.2565x; 1.0423x over previous
#include <cuda_runtime.h>
#include <cstdint>

#define B_  8
#define N_  4096
#define L_  4096
#define GC_ 32
#define IC_ 256

// K/Q rows stored in fragment order: word w -> perm16(w) = ((w&3)<<2)|(w>>2)
// V' pairs stored with in-block perm: j -> ((j&3)<<1)|((j>>2)&1)
__device__ uint32_t g_Qb [B_*N_*16];      // [b][n][w'] f16x2 (Q*QSCALE)
__device__ uint32_t g_Kb [B_*L_*16];      // [b][l][w'] f16x2
__device__ float    g_VTc[B_*GC_*L_];     // [b][c][l] raw f32 (channel-major)
__device__ uint32_t g_Vb [B_*GC_*(L_/2)]; // [b][c][l2'] f16x2 of V*Dinv

#define QSCALE 0.2550668292560464f  // (1/sqrt(32)) * log2(e)

// ===========================================================================
// helpers
// ===========================================================================
__device__ __forceinline__ uint32_t smem_u32(const void* p) {
    uint32_t a;
    asm("{ .reg .u64 t; cvta.to.shared.u64 t, %1; cvt.u32.u64 %0, t; }"
        : "=r"(a) : "l"(p));
    return a;
}
__device__ __forceinline__ uint32_t pk_h2(float hi, float lo) {
    uint32_t r;
    asm("cvt.rn.f16x2.f32 %0, %1, %2;" : "=r"(r) : "f"(hi), "f"(lo));
    return r;
}
__device__ __forceinline__ uint32_t ex2h2(uint32_t x) {
    uint32_t y;
    asm("ex2.approx.f16x2 %0, %1;" : "=r"(y) : "r"(x));
    return y;
}
__device__ __forceinline__ uint32_t hadd2(uint32_t a, uint32_t b) {
    uint32_t r;
    asm("add.rn.f16x2 %0, %1, %2;" : "=r"(r) : "r"(a), "r"(b));
    return r;
}
__device__ __forceinline__ float hsum2f(uint32_t h2) {
    float lo, hi;
    asm("{ .reg .b16 l, h;\n\t mov.b32 {l, h}, %2;\n\t"
        "cvt.f32.f16 %0, l;\n\t cvt.f32.f16 %1, h; }"
        : "=f"(lo), "=f"(hi) : "r"(h2));
    return lo + hi;
}
__device__ __forceinline__ void mma_f16(float c[4], const uint32_t a[4],
                                        uint32_t b0, uint32_t b1) {
    asm volatile("mma.sync.aligned.m16n8k16.row.col.f32.f16.f16.f32 "
        "{%0,%1,%2,%3}, {%4,%5,%6,%7}, {%8,%9}, {%0,%1,%2,%3};"
        : "+f"(c[0]), "+f"(c[1]), "+f"(c[2]), "+f"(c[3])
        : "r"(a[0]), "r"(a[1]), "r"(a[2]), "r"(a[3]), "r"(b0), "r"(b1));
}
__device__ __forceinline__ void cp16(uint32_t s, const void* g) {
    asm volatile("cp.async.ca.shared.global [%0], [%1], 16;"
                 :: "r"(s), "l"(g) : "memory");
}
#define CP_COMMIT() asm volatile("cp.async.commit_group;" ::: "memory")
#define CP_WAIT1()  asm volatile("cp.async.wait_group 1;" ::: "memory")
#define CP_WAIT0()  asm volatile("cp.async.wait_group 0;" ::: "memory")

// ===========================================================================
// Kernel 1: Q projection -> f16x2, QSCALE folded, fragment-order layout
// ===========================================================================
__global__ __launch_bounds__(256) void k_proj_q(
    const float* __restrict__ graph, const float* __restrict__ Wq,
    const float* __restrict__ bq)
{
    __shared__ float WqS[GC_*33];
    __shared__ float gS[64*GC_];
    int b  = blockIdx.x >> 6;
    int n0 = (blockIdx.x & 63) * 64;
    int tid = threadIdx.x;

    for (int i = tid; i < GC_*GC_; i += 256)
        WqS[(i>>5)*33 + (i&31)] = Wq[i];
    const float* gp = graph + ((long)b*N_ + n0)*GC_;
    for (int i = tid; i < 64*GC_; i += 256) gS[i] = gp[i];
    __syncthreads();

    int o2 = tid & 15, nb = tid >> 4;
    int po2 = ((o2 & 3) << 2) | (o2 >> 2);   // perm16
    float b0 = bq[2*o2], b1 = bq[2*o2 + 1];
    #pragma unroll
    for (int j = 0; j < 4; j++) {
        int n = nb + 16*j;
        float a0 = b0, a1 = b1;
        #pragma unroll
        for (int c = 0; c < 32; c++) {
            float gv = gS[n*32 + c];
            a0 += WqS[(2*o2    )*33 + c] * gv;
            a1 += WqS[(2*o2 + 1)*33 + c] * gv;
        }
        g_Qb[((long)b*N_ + n0 + n)*16 + po2] = pk_h2(a1*QSCALE, a0*QSCALE);
    }
}

// ===========================================================================
// Kernel 2: K/V projection via f16 MMA. K stored fragment-order.
// ===========================================================================
#define PW 132
#define PI 260

__global__ __launch_bounds__(256, 1) void k_proj_kv_mma(
    const float* __restrict__ img,
    const float* __restrict__ Wk, const float* __restrict__ bk,
    const float* __restrict__ Wv, const float* __restrict__ bv)
{
    extern __shared__ uint32_t shm[];
    uint32_t* Wsm  = shm;
    float*    img0 = (float*)(shm + 64*PW);
    float*    img1 = img0 + 64*PI;

    int tid = threadIdx.x, w = tid >> 5, lane = tid & 31;
    int q = lane & 3, g = lane >> 2;
    int b = blockIdx.x >> 4, l0 = (blockIdx.x & 15) * 256;

    #pragma unroll
    for (int t = 0; t < 32; t++) {
        int u = tid + t*256;
        int o = u >> 7, c2 = u & 127;
        const float* src = (o < 32) ? (Wk + o*IC_ + 2*c2) : (Wv + (o-32)*IC_ + 2*c2);
        float2 v = *(const float2*)src;
        Wsm[o*PW + c2] = pk_h2(v.y, v.x);
    }

    auto pref = [&](int ks, float* dstbuf) {
        const float* src = img + ((long)b*IC_ + ks*64)*L_ + l0;
        uint32_t dstb = smem_u32(dstbuf);
        #pragma unroll
        for (int t = 0; t < 16; t++) {
            int u = tid + t*256;
            int c = u >> 6, col = (u & 63) * 4;
            cp16(dstb + (c*PI + col)*4, src + (long)c*L_ + col);
        }
        CP_COMMIT();
    };
    pref(0, img0);

    float C[4][4][4];
    #pragma unroll
    for (int mt = 0; mt < 4; mt++) {
        const float* bias = (mt < 2) ? bk : bv;
        int ob = (mt & 1) * 16;
        float blo = bias[ob + g], bhi = bias[ob + 8 + g];
        #pragma unroll
        for (int nt = 0; nt < 4; nt++) {
            C[mt][nt][0] = C[mt][nt][1] = blo;
            C[mt][nt][2] = C[mt][nt][3] = bhi;
        }
    }
    __syncthreads();

    int lw = w * 32;
    for (int ks = 0; ks < 4; ks++) {
        if (ks < 3) { pref(ks + 1, (ks & 1) ? img0 : img1); CP_WAIT1(); }
        else CP_WAIT0();
        __syncthreads();
        const float* I = (ks & 1) ? img1 : img0;
        #pragma unroll
        for (int kk = 0; kk < 4; kk++) {
            uint32_t A[4][4];
            #pragma unroll
            for (int mt = 0; mt < 4; mt++) {
                const uint32_t* wp = Wsm + (mt*16)*PW + ks*32 + kk*8;
                A[mt][0] = wp[ g   *PW + q];
                A[mt][1] = wp[(g+8)*PW + q];
                A[mt][2] = wp[ g   *PW + q + 4];
                A[mt][3] = wp[(g+8)*PW + q + 4];
            }
            uint32_t Bf[4][2];
            #pragma unroll
            for (int nt = 0; nt < 4; nt++) {
                int l = lw + nt*8 + g;
                const float* r0 = I + (kk*16 + 2*q    )*PI + l;
                const float* r1 = I + (kk*16 + 2*q + 8)*PI + l;
                Bf[nt][0] = pk_h2(r0[PI], r0[0]);
                Bf[nt][1] = pk_h2(r1[PI], r1[0]);
            }
            #pragma unroll
            for (int mt = 0; mt < 4; mt++)
                #pragma unroll
                for (int nt = 0; nt < 4; nt++)
                    mma_f16(C[mt][nt], A[mt], Bf[nt][0], Bf[nt][1]);
        }
        __syncthreads();
    }

    // K epilogue: quad shfl-transpose -> g_Kb[l][w'] (fragment-order)
    bool odd = (g & 1);
    int sA = 8*q + (g >> 1), sB = sA + 4;
    #pragma unroll
    for (int mt = 0; mt < 2; mt++)
        #pragma unroll
        for (int nt = 0; nt < 4; nt++) {
            float* c = C[mt][nt];
            float t0 = __shfl_sync(~0u, c[0], sA), t1 = __shfl_sync(~0u, c[1], sA);
            float t2 = __shfl_sync(~0u, c[0], sB), t3 = __shfl_sync(~0u, c[1], sB);
            float t4 = __shfl_sync(~0u, c[2], sA), t5 = __shfl_sync(~0u, c[3], sA);
            float t6 = __shfl_sync(~0u, c[2], sB), t7 = __shfl_sync(~0u, c[3], sB);
            float lo0 = odd ? t1 : t0, hi0 = odd ? t3 : t2;
            float lo1 = odd ? t5 : t4, hi1 = odd ? t7 : t6;
            long l = (long)b*L_ + l0 + lw + nt*8 + g;
            g_Kb[l*16 + 4*q + 2*mt    ] = pk_h2(hi0, lo0);
            g_Kb[l*16 + 4*q + 2*mt + 1] = pk_h2(hi1, lo1);
        }
    #pragma unroll
    for (int mt = 2; mt < 4; mt++)
        #pragma unroll
        for (int nt = 0; nt < 4; nt++) {
            int c = (mt - 2)*16 + g;
            long base = ((long)b*GC_ + c)*L_ + l0 + lw + nt*8 + 2*q;
            *(float2*)(g_VTc + base)         = make_float2(C[mt][nt][0], C[mt][nt][1]);
            *(float2*)(g_VTc + base + 8*L_)  = make_float2(C[mt][nt][2], C[mt][nt][3]);
        }
}

// ===========================================================================
// Kernel 3: stats, 512 threads. Fragment-order Q smem (KP=16, LDS.128
// B-frags), f16x2 exp. V' written with in-block pair permutation.
// ===========================================================================
__global__ __launch_bounds__(512, 1) void k_stats_mma()
{
    __shared__ __align__(16) uint32_t Qs[2][128*16];
    __shared__ float dS[2][256];
    __shared__ float dinvS[256];
    int tid = threadIdx.x, w = tid >> 5, lane = tid & 31;
    int wp = w & 7, wh = w >> 3;
    int q = lane & 3, g = lane >> 2;
    int b = blockIdx.x >> 4, l0 = (blockIdx.x & 15) * 256;
    uint32_t qs_b = smem_u32(Qs);

    uint32_t A[2][2][4];
    #pragma unroll
    for (int mt = 0; mt < 2; mt++) {
        const uint32_t* kp = g_Kb + ((long)b*L_ + l0 + wp*32 + mt*16)*16;
        #pragma unroll
        for (int kk = 0; kk < 2; kk++) {
            A[mt][kk][0] = kp[ g   *16 + 4*q + 2*kk    ];
            A[mt][kk][1] = kp[(g+8)*16 + 4*q + 2*kk    ];
            A[mt][kk][2] = kp[ g   *16 + 4*q + 2*kk + 1];
            A[mt][kk][3] = kp[(g+8)*16 + 4*q + 2*kk + 1];
        }
    }

    auto prefetch = [&](int nc, int buf) {
        const uint32_t* src = g_Qb + ((long)b*N_ + nc*128)*16;
        int r = tid >> 2, t = tid & 3;
        cp16(qs_b + (buf*128*16 + r*16 + 4*t)*4, src + r*16 + 4*t);
        CP_COMMIT();
    };
    prefetch(0, 0);

    float d[2][2] = {{0.f,0.f},{0.f,0.f}};
    int j0 = wh * 8;
    for (int nc = 0; nc < 32; nc++) {
        if (nc < 31) { prefetch(nc + 1, (nc + 1) & 1); CP_WAIT1(); }
        else CP_WAIT0();
        __syncthreads();
        const uint32_t* Q = &Qs[nc & 1][0];
        uint32_t dh[2][2] = {{0u,0u},{0u,0u}};
        #pragma unroll 4
        for (int jj = 0; jj < 8; jj++) {
            int j = j0 + jj;
            uint4 f = *(const uint4*)&Q[(g + 8*j)*16 + 4*q];
            #pragma unroll
            for (int mt = 0; mt < 2; mt++) {
                float c[4] = {0.f, 0.f, 0.f, 0.f};
                mma_f16(c, A[mt][0], f.x, f.y);
                mma_f16(c, A[mt][1], f.z, f.w);
                dh[mt][0] = hadd2(dh[mt][0], ex2h2(pk_h2(c[1], c[0])));
                dh[mt][1] = hadd2(dh[mt][1], ex2h2(pk_h2(c[3], c[2])));
            }
        }
        #pragma unroll
        for (int mt = 0; mt < 2; mt++) {
            d[mt][0] += hsum2f(dh[mt][0]);
            d[mt][1] += hsum2f(dh[mt][1]);
        }
        __syncthreads();
    }
    #pragma unroll
    for (int mt = 0; mt < 2; mt++) {
        #pragma unroll
        for (int h = 0; h < 2; h++) {
            float dv = d[mt][h];
            dv += __shfl_xor_sync(~0u, dv, 1);
            dv += __shfl_xor_sync(~0u, dv, 2);
            if (q == 0) dS[wh][wp*32 + mt*16 + h*8 + g] = dv;
        }
    }
    __syncthreads();
    if (tid < 256) dinvS[tid] = 1.0f / (dS[0][tid] + dS[1][tid]);
    __syncthreads();

    // V' pack: destination index permuted within 8-word blocks
    uint32_t* dst = g_Vb + ((long)b*GC_)*(L_/2) + (l0 >> 1);
    const float* vsrc = g_VTc + ((long)b*GC_)*L_ + l0;
    #pragma unroll
    for (int t = 0; t < 8; t++) {
        int u = tid + t*512;
        int c = u >> 7, l2 = u & 127;
        int l2p = (l2 & ~7) | ((l2 & 3) << 1) | ((l2 >> 2) & 1);
        float2 v = *(const float2*)(vsrc + (long)c*L_ + 2*l2);
        dst[(long)c*(L_/2) + l2p] =
            pk_h2(v.y * dinvS[2*l2 + 1], v.x * dinvS[2*l2]);
    }
}

// ===========================================================================
// Kernel 4: final, 512 threads. Fragment-order layouts (K: LDS.128,
// V: LDS.64), software-pipelined exp: GEMM2(ss-1) consumes prev A2.
// msgP pitch 34 (even -> float2 8B-aligned).
// ===========================================================================
#define KP 16
#define VP 72
#define VB_OFF (2*128*KP)
#define SH_WORDS (2*128*KP + 2*32*VP)   // 8704 == 256*34 (msgP reuse)
#define MP 34

__global__ __launch_bounds__(512, 1) void k_final_mma(
    const float* __restrict__ graph, const float* __restrict__ Wc,
    const float* __restrict__ bc, float* __restrict__ out)
{
    __shared__ __align__(16) uint32_t SH[SH_WORDS];
    __shared__ uint32_t Wb[32*17];
    int tid = threadIdx.x, w = tid >> 5, lane = tid & 31;
    int wp = w & 7, wh = w >> 3;
    int q = lane & 3, g = lane >> 2;
    int b = blockIdx.x >> 4, n0 = (blockIdx.x & 15) * 256;
    uint32_t sh_b = smem_u32(SH);

    uint32_t A[2][2][4];
    #pragma unroll
    for (int mt = 0; mt < 2; mt++) {
        const uint32_t* qp = g_Qb + ((long)b*N_ + n0 + wp*32 + mt*16)*16;
        #pragma unroll
        for (int kk = 0; kk < 2; kk++) {
            A[mt][kk][0] = qp[ g   *16 + 4*q + 2*kk    ];
            A[mt][kk][1] = qp[(g+8)*16 + 4*q + 2*kk    ];
            A[mt][kk][2] = qp[ g   *16 + 4*q + 2*kk + 1];
            A[mt][kk][3] = qp[(g+8)*16 + 4*q + 2*kk + 1];
        }
    }
    for (int i = tid; i < 32*16; i += 512) {
        int o = i >> 4, c2 = i & 15;
        Wb[o*17 + c2] = pk_h2(Wc[o*32 + 2*c2 + 1], Wc[o*32 + 2*c2]);
    }

    const uint32_t* vbsrc = g_Vb + ((long)b*GC_)*(L_/2);
    auto prefetch = [&](int lc, int buf) {
        const uint32_t* ksrc = g_Kb + ((long)b*L_ + lc*128)*16;
        {
            int r = tid >> 2, t = tid & 3;
            cp16(sh_b + (buf*128*KP + r*KP + 4*t)*4, ksrc + r*16 + 4*t);
        }
        {
            int c = tid >> 4, t2 = tid & 15;
            cp16(sh_b + (VB_OFF + buf*32*VP + c*VP + 4*t2)*4,
                 vbsrc + (long)c*(L_/2) + lc*64 + 4*t2);
        }
        CP_COMMIT();
    };
    prefetch(0, 0);

    float mc[2][4][4];
    #pragma unroll
    for (int mt = 0; mt < 2; mt++)
        #pragma unroll
        for (int cf = 0; cf < 4; cf++)
            #pragma unroll
            for (int x = 0; x < 4; x++) mc[mt][cf][x] = 0.f;

    int s0 = wh * 4;
    for (int lc = 0; lc < 32; lc++) {
        if (lc < 31) { prefetch(lc + 1, (lc + 1) & 1); CP_WAIT1(); }
        else CP_WAIT0();
        __syncthreads();
        const uint32_t* K = SH + (lc & 1)*128*KP;
        const uint32_t* V = SH + VB_OFF + (lc & 1)*32*VP;

        uint32_t A2p[2][4];   // exp fragments of previous ss
        #pragma unroll
        for (int ss = 0; ss < 4; ss++) {
            int s = s0 + ss;
            uint4 fa = *(const uint4*)&K[(g + 16*s    )*KP + 4*q];
            uint4 fb = *(const uint4*)&K[(g + 16*s + 8)*KP + 4*q];
            float c[2][2][4];
            #pragma unroll
            for (int mt = 0; mt < 2; mt++) {
                #pragma unroll
                for (int h = 0; h < 2; h++)
                    #pragma unroll
                    for (int x = 0; x < 4; x++) c[mt][h][x] = 0.f;
                mma_f16(c[mt][0], A[mt][0], fa.x, fa.y);
                mma_f16(c[mt][0], A[mt][1], fa.z, fa.w);
                mma_f16(c[mt][1], A[mt][0], fb.x, fb.y);
                mma_f16(c[mt][1], A[mt][1], fb.z, fb.w);
            }
            if (ss > 0) {   // GEMM2 for previous ss (A2p ready, no MUFU wait)
                int sp = s - 1;
                #pragma unroll
                for (int cf = 0; cf < 4; cf++) {
                    uint2 vv = *(const uint2*)&V[(g + 8*cf)*VP + 8*sp + 2*q];
                    #pragma unroll
                    for (int mt = 0; mt < 2; mt++)
                        mma_f16(mc[mt][cf], A2p[mt], vv.x, vv.y);
                }
            }
            #pragma unroll
            for (int mt = 0; mt < 2; mt++) {
                A2p[mt][0] = ex2h2(pk_h2(c[mt][0][1], c[mt][0][0]));
                A2p[mt][1] = ex2h2(pk_h2(c[mt][0][3], c[mt][0][2]));
                A2p[mt][2] = ex2h2(pk_h2(c[mt][1][1], c[mt][1][0]));
                A2p[mt][3] = ex2h2(pk_h2(c[mt][1][3], c[mt][1][2]));
            }
        }
        {   // flush GEMM2 for last ss of this lc (V buffer still live)
            int sp = s0 + 3;
            #pragma unroll
            for (int cf = 0; cf < 4; cf++) {
                uint2 vv = *(const uint2*)&V[(g + 8*cf)*VP + 8*sp + 2*q];
                #pragma unroll
                for (int mt = 0; mt < 2; mt++)
                    mma_f16(mc[mt][cf], A2p[mt], vv.x, vv.y);
            }
        }
        __syncthreads();
    }

    // combine warp-pair partials via smem (reuse SH as msgP[256][MP])
    float* msgP = (float*)SH;
    if (wh == 1) {
        #pragma unroll
        for (int mt = 0; mt < 2; mt++) {
            int rb = wp*32 + mt*16;
            #pragma unroll
            for (int cf = 0; cf < 4; cf++) {
                int col = cf*8 + 2*q;
                *(float2*)&msgP[(rb + g    )*MP + col] =
                    make_float2(mc[mt][cf][0], mc[mt][cf][1]);
                *(float2*)&msgP[(rb + g + 8)*MP + col] =
                    make_float2(mc[mt][cf][2], mc[mt][cf][3]);
            }
        }
    }
    __syncthreads();

    if (wh == 0) {
        #pragma unroll
        for (int mt = 0; mt < 2; mt++) {
            int rb = wp*32 + mt*16;
            #pragma unroll
            for (int cf = 0; cf < 4; cf++) {
                int col = cf*8 + 2*q;
                float2 p0 = *(const float2*)&msgP[(rb + g    )*MP + col];
                float2 p1 = *(const float2*)&msgP[(rb + g + 8)*MP + col];
                mc[mt][cf][0] += p0.x; mc[mt][cf][1] += p0.y;
                mc[mt][cf][2] += p1.x; mc[mt][cf][3] += p1.y;
            }
        }
        #pragma unroll
        for (int mt = 0; mt < 2; mt++) {
            uint32_t A3[2][4];
            #pragma unroll
            for (int t = 0; t < 2; t++) {
                A3[t][0] = pk_h2(mc[mt][2*t  ][1], mc[mt][2*t  ][0]);
                A3[t][1] = pk_h2(mc[mt][2*t  ][3], mc[mt][2*t  ][2]);
                A3[t][2] = pk_h2(mc[mt][2*t+1][1], mc[mt][2*t+1][0]);
                A3[t][3] = pk_h2(mc[mt][2*t+1][3], mc[mt][2*t+1][2]);
            }
            long nbase = (long)b*N_ + n0 + wp*32 + mt*16;
            const float* gp = graph + nbase*32;
            float* op = out + nbase*32;
            #pragma unroll
            for (int of = 0; of < 4; of++) {
                int col = 8*of + 2*q;
                float bc0 = bc[col], bc1 = bc[col + 1];
                float2 gr0 = *(const float2*)(gp + g*32 + col);
                float2 gr1 = *(const float2*)(gp + (g + 8)*32 + col);
                float c[4] = { gr0.x + bc0, gr0.y + bc1, gr1.x + bc0, gr1.y + bc1 };
                #pragma unroll
                for (int t = 0; t < 2; t++) {
                    uint32_t b0 = Wb[(g + 8*of)*17 + 8*t + q    ];
                    uint32_t b1 = Wb[(g + 8*of)*17 + 8*t + q + 4];
                    mma_f16(c, A3[t], b0, b1);
                }
                *(float2*)(op + g*32 + col)       = make_float2(c[0], c[1]);
                *(float2*)(op + (g + 8)*32 + col) = make_float2(c[2], c[3]);
            }
        }
    }
}

// ===========================================================================
extern "C" void kernel_launch(void* const* d_in, const int* in_sizes, int n_in,
                              void* d_out, int out_size)
{
    const float* graph = (const float*)d_in[0];
    const float* img   = (const float*)d_in[1];
    const float* Wq    = (const float*)d_in[2];
    const float* bq    = (const float*)d_in[3];
    const float* Wk    = (const float*)d_in[4];
    const float* bk    = (const float*)d_in[5];
    const float* Wv    = (const float*)d_in[6];
    const float* bv    = (const float*)d_in[7];
    const float* Wc    = (const float*)d_in[8];
    const float* bc    = (const float*)d_in[9];
    float* out = (float*)d_out;

    size_t proj_smem = (64*PW + 2*64*PI) * sizeof(uint32_t);
    static int attr_set = 0;
    if (!attr_set) {
        cudaFuncSetAttribute(k_proj_kv_mma,
                             cudaFuncAttributeMaxDynamicSharedMemorySize,
                             (int)proj_smem);
        attr_set = 1;
    }

    k_proj_q     <<<B_*(N_/64), 256>>>(graph, Wq, bq);
    k_proj_kv_mma<<<B_*(L_/256), 256, proj_smem>>>(img, Wk, bk, Wv, bv);
    k_stats_mma  <<<B_*(L_/256), 512>>>();
    k_final_mma  <<<B_*(N_/256), 512>>>(graph, Wc, bc, out);
}

// round 14
// speedup vs baseline: 1.3154x; 1.0469x over previous
#include <cuda_runtime.h>
#include <cstdint>

#define B_  8
#define N_  4096
#define L_  4096
#define GC_ 32
#define IC_ 256

// K/Q rows stored in fragment order: word w -> perm16(w) = ((w&3)<<2)|(w>>2)
// V' pairs stored with in-block perm: j -> ((j&3)<<1)|((j>>2)&1)
__device__ uint32_t g_Qb [B_*N_*16];      // [b][n][w'] f16x2 (Q*QSCALE)
__device__ uint32_t g_Kb [B_*L_*16];      // [b][l][w'] f16x2
__device__ float    g_VTc[B_*GC_*L_];     // [b][c][l] raw f32 (channel-major)
__device__ uint32_t g_Vb [B_*GC_*(L_/2)]; // [b][c][l2'] f16x2 of V*Dinv

#define QSCALE 0.2550668292560464f  // (1/sqrt(32)) * log2(e)

// ===========================================================================
// helpers
// ===========================================================================
__device__ __forceinline__ uint32_t smem_u32(const void* p) {
    uint32_t a;
    asm("{ .reg .u64 t; cvta.to.shared.u64 t, %1; cvt.u32.u64 %0, t; }"
        : "=r"(a) : "l"(p));
    return a;
}
__device__ __forceinline__ uint32_t pk_h2(float hi, float lo) {
    uint32_t r;
    asm("cvt.rn.f16x2.f32 %0, %1, %2;" : "=r"(r) : "f"(hi), "f"(lo));
    return r;
}
__device__ __forceinline__ uint32_t ex2h2(uint32_t x) {
    uint32_t y;
    asm("ex2.approx.f16x2 %0, %1;" : "=r"(y) : "r"(x));
    return y;
}
__device__ __forceinline__ uint32_t hadd2(uint32_t a, uint32_t b) {
    uint32_t r;
    asm("add.rn.f16x2 %0, %1, %2;" : "=r"(r) : "r"(a), "r"(b));
    return r;
}
__device__ __forceinline__ float hsum2f(uint32_t h2) {
    float lo, hi;
    asm("{ .reg .b16 l, h;\n\t mov.b32 {l, h}, %2;\n\t"
        "cvt.f32.f16 %0, l;\n\t cvt.f32.f16 %1, h; }"
        : "=f"(lo), "=f"(hi) : "r"(h2));
    return lo + hi;
}
__device__ __forceinline__ void mma_f16(float c[4], const uint32_t a[4],
                                        uint32_t b0, uint32_t b1) {
    asm volatile("mma.sync.aligned.m16n8k16.row.col.f32.f16.f16.f32 "
        "{%0,%1,%2,%3}, {%4,%5,%6,%7}, {%8,%9}, {%0,%1,%2,%3};"
        : "+f"(c[0]), "+f"(c[1]), "+f"(c[2]), "+f"(c[3])
        : "r"(a[0]), "r"(a[1]), "r"(a[2]), "r"(a[3]), "r"(b0), "r"(b1));
}
__device__ __forceinline__ void cp16(uint32_t s, const void* g) {
    asm volatile("cp.async.ca.shared.global [%0], [%1], 16;"
                 :: "r"(s), "l"(g) : "memory");
}
#define CP_COMMIT() asm volatile("cp.async.commit_group;" ::: "memory")
#define CP_WAIT1()  asm volatile("cp.async.wait_group 1;" ::: "memory")
#define CP_WAIT0()  asm volatile("cp.async.wait_group 0;" ::: "memory")

// ===========================================================================
// Kernel 1: Q projection -> f16x2, QSCALE folded, fragment-order layout
// ===========================================================================
__global__ __launch_bounds__(256) void k_proj_q(
    const float* __restrict__ graph, const float* __restrict__ Wq,
    const float* __restrict__ bq)
{
    __shared__ float WqS[GC_*33];
    __shared__ float gS[64*GC_];
    int b  = blockIdx.x >> 6;
    int n0 = (blockIdx.x & 63) * 64;
    int tid = threadIdx.x;

    for (int i = tid; i < GC_*GC_; i += 256)
        WqS[(i>>5)*33 + (i&31)] = Wq[i];
    const float* gp = graph + ((long)b*N_ + n0)*GC_;
    for (int i = tid; i < 64*GC_; i += 256) gS[i] = gp[i];
    __syncthreads();

    int o2 = tid & 15, nb = tid >> 4;
    int po2 = ((o2 & 3) << 2) | (o2 >> 2);   // perm16
    float b0 = bq[2*o2], b1 = bq[2*o2 + 1];
    #pragma unroll
    for (int j = 0; j < 4; j++) {
        int n = nb + 16*j;
        float a0 = b0, a1 = b1;
        #pragma unroll
        for (int c = 0; c < 32; c++) {
            float gv = gS[n*32 + c];
            a0 += WqS[(2*o2    )*33 + c] * gv;
            a1 += WqS[(2*o2 + 1)*33 + c] * gv;
        }
        g_Qb[((long)b*N_ + n0 + n)*16 + po2] = pk_h2(a1*QSCALE, a0*QSCALE);
    }
}

// ===========================================================================
// Kernel 2: K/V projection via f16 MMA. K stored fragment-order.
// ===========================================================================
#define PW 132
#define PI 260

__global__ __launch_bounds__(256, 1) void k_proj_kv_mma(
    const float* __restrict__ img,
    const float* __restrict__ Wk, const float* __restrict__ bk,
    const float* __restrict__ Wv, const float* __restrict__ bv)
{
    extern __shared__ uint32_t shm[];
    uint32_t* Wsm  = shm;
    float*    img0 = (float*)(shm + 64*PW);
    float*    img1 = img0 + 64*PI;

    int tid = threadIdx.x, w = tid >> 5, lane = tid & 31;
    int q = lane & 3, g = lane >> 2;
    int b = blockIdx.x >> 4, l0 = (blockIdx.x & 15) * 256;

    #pragma unroll
    for (int t = 0; t < 32; t++) {
        int u = tid + t*256;
        int o = u >> 7, c2 = u & 127;
        const float* src = (o < 32) ? (Wk + o*IC_ + 2*c2) : (Wv + (o-32)*IC_ + 2*c2);
        float2 v = *(const float2*)src;
        Wsm[o*PW + c2] = pk_h2(v.y, v.x);
    }

    auto pref = [&](int ks, float* dstbuf) {
        const float* src = img + ((long)b*IC_ + ks*64)*L_ + l0;
        uint32_t dstb = smem_u32(dstbuf);
        #pragma unroll
        for (int t = 0; t < 16; t++) {
            int u = tid + t*256;
            int c = u >> 6, col = (u & 63) * 4;
            cp16(dstb + (c*PI + col)*4, src + (long)c*L_ + col);
        }
        CP_COMMIT();
    };
    pref(0, img0);

    float C[4][4][4];
    #pragma unroll
    for (int mt = 0; mt < 4; mt++) {
        const float* bias = (mt < 2) ? bk : bv;
        int ob = (mt & 1) * 16;
        float blo = bias[ob + g], bhi = bias[ob + 8 + g];
        #pragma unroll
        for (int nt = 0; nt < 4; nt++) {
            C[mt][nt][0] = C[mt][nt][1] = blo;
            C[mt][nt][2] = C[mt][nt][3] = bhi;
        }
    }
    __syncthreads();

    int lw = w * 32;
    for (int ks = 0; ks < 4; ks++) {
        if (ks < 3) { pref(ks + 1, (ks & 1) ? img0 : img1); CP_WAIT1(); }
        else CP_WAIT0();
        __syncthreads();
        const float* I = (ks & 1) ? img1 : img0;
        #pragma unroll
        for (int kk = 0; kk < 4; kk++) {
            uint32_t A[4][4];
            #pragma unroll
            for (int mt = 0; mt < 4; mt++) {
                const uint32_t* wp = Wsm + (mt*16)*PW + ks*32 + kk*8;
                A[mt][0] = wp[ g   *PW + q];
                A[mt][1] = wp[(g+8)*PW + q];
                A[mt][2] = wp[ g   *PW + q + 4];
                A[mt][3] = wp[(g+8)*PW + q + 4];
            }
            uint32_t Bf[4][2];
            #pragma unroll
            for (int nt = 0; nt < 4; nt++) {
                int l = lw + nt*8 + g;
                const float* r0 = I + (kk*16 + 2*q    )*PI + l;
                const float* r1 = I + (kk*16 + 2*q + 8)*PI + l;
                Bf[nt][0] = pk_h2(r0[PI], r0[0]);
                Bf[nt][1] = pk_h2(r1[PI], r1[0]);
            }
            #pragma unroll
            for (int mt = 0; mt < 4; mt++)
                #pragma unroll
                for (int nt = 0; nt < 4; nt++)
                    mma_f16(C[mt][nt], A[mt], Bf[nt][0], Bf[nt][1]);
        }
        __syncthreads();
    }

    // K epilogue: quad shfl-transpose -> g_Kb[l][w'] (fragment-order)
    bool odd = (g & 1);
    int sA = 8*q + (g >> 1), sB = sA + 4;
    #pragma unroll
    for (int mt = 0; mt < 2; mt++)
        #pragma unroll
        for (int nt = 0; nt < 4; nt++) {
            float* c = C[mt][nt];
            float t0 = __shfl_sync(~0u, c[0], sA), t1 = __shfl_sync(~0u, c[1], sA);
            float t2 = __shfl_sync(~0u, c[0], sB), t3 = __shfl_sync(~0u, c[1], sB);
            float t4 = __shfl_sync(~0u, c[2], sA), t5 = __shfl_sync(~0u, c[3], sA);
            float t6 = __shfl_sync(~0u, c[2], sB), t7 = __shfl_sync(~0u, c[3], sB);
            float lo0 = odd ? t1 : t0, hi0 = odd ? t3 : t2;
            float lo1 = odd ? t5 : t4, hi1 = odd ? t7 : t6;
            long l = (long)b*L_ + l0 + lw + nt*8 + g;
            g_Kb[l*16 + 4*q + 2*mt    ] = pk_h2(hi0, lo0);
            g_Kb[l*16 + 4*q + 2*mt + 1] = pk_h2(hi1, lo1);
        }
    #pragma unroll
    for (int mt = 2; mt < 4; mt++)
        #pragma unroll
        for (int nt = 0; nt < 4; nt++) {
            int c = (mt - 2)*16 + g;
            long base = ((long)b*GC_ + c)*L_ + l0 + lw + nt*8 + 2*q;
            *(float2*)(g_VTc + base)         = make_float2(C[mt][nt][0], C[mt][nt][1]);
            *(float2*)(g_VTc + base + 8*L_)  = make_float2(C[mt][nt][2], C[mt][nt][3]);
        }
}

// ===========================================================================
// Kernel 3: stats, 512 threads, 256-n tiles (16 iterations).
// Fragment-order Q smem (LDS.128 B-frags), f16x2 exp.
// ===========================================================================
__global__ __launch_bounds__(512, 1) void k_stats_mma()
{
    __shared__ __align__(16) uint32_t Qs[2][256*16];
    __shared__ float dS[2][256];
    __shared__ float dinvS[256];
    int tid = threadIdx.x, w = tid >> 5, lane = tid & 31;
    int wp = w & 7, wh = w >> 3;
    int q = lane & 3, g = lane >> 2;
    int b = blockIdx.x >> 4, l0 = (blockIdx.x & 15) * 256;
    uint32_t qs_b = smem_u32(Qs);

    uint32_t A[2][2][4];
    #pragma unroll
    for (int mt = 0; mt < 2; mt++) {
        const uint32_t* kp = g_Kb + ((long)b*L_ + l0 + wp*32 + mt*16)*16;
        #pragma unroll
        for (int kk = 0; kk < 2; kk++) {
            A[mt][kk][0] = kp[ g   *16 + 4*q + 2*kk    ];
            A[mt][kk][1] = kp[(g+8)*16 + 4*q + 2*kk    ];
            A[mt][kk][2] = kp[ g   *16 + 4*q + 2*kk + 1];
            A[mt][kk][3] = kp[(g+8)*16 + 4*q + 2*kk + 1];
        }
    }

    auto prefetch = [&](int nc, int buf) {
        const uint32_t* src = g_Qb + ((long)b*N_ + nc*256)*16;
        #pragma unroll
        for (int it = 0; it < 2; it++) {
            int u = tid + it*512;
            int r = u >> 2, t = u & 3;
            cp16(qs_b + (buf*256*16 + r*16 + 4*t)*4, src + r*16 + 4*t);
        }
        CP_COMMIT();
    };
    prefetch(0, 0);

    float d[2][2] = {{0.f,0.f},{0.f,0.f}};
    int j0 = wh * 16;
    for (int nc = 0; nc < 16; nc++) {
        if (nc < 15) { prefetch(nc + 1, (nc + 1) & 1); CP_WAIT1(); }
        else CP_WAIT0();
        __syncthreads();
        const uint32_t* Q = &Qs[nc & 1][0];
        uint32_t dh[2][2] = {{0u,0u},{0u,0u}};
        #pragma unroll 4
        for (int jj = 0; jj < 16; jj++) {
            int j = j0 + jj;
            uint4 f = *(const uint4*)&Q[(g + 8*j)*16 + 4*q];
            #pragma unroll
            for (int mt = 0; mt < 2; mt++) {
                float c[4] = {0.f, 0.f, 0.f, 0.f};
                mma_f16(c, A[mt][0], f.x, f.y);
                mma_f16(c, A[mt][1], f.z, f.w);
                dh[mt][0] = hadd2(dh[mt][0], ex2h2(pk_h2(c[1], c[0])));
                dh[mt][1] = hadd2(dh[mt][1], ex2h2(pk_h2(c[3], c[2])));
            }
        }
        #pragma unroll
        for (int mt = 0; mt < 2; mt++) {
            d[mt][0] += hsum2f(dh[mt][0]);
            d[mt][1] += hsum2f(dh[mt][1]);
        }
        __syncthreads();
    }
    #pragma unroll
    for (int mt = 0; mt < 2; mt++) {
        #pragma unroll
        for (int h = 0; h < 2; h++) {
            float dv = d[mt][h];
            dv += __shfl_xor_sync(~0u, dv, 1);
            dv += __shfl_xor_sync(~0u, dv, 2);
            if (q == 0) dS[wh][wp*32 + mt*16 + h*8 + g] = dv;
        }
    }
    __syncthreads();
    if (tid < 256) dinvS[tid] = 1.0f / (dS[0][tid] + dS[1][tid]);
    __syncthreads();

    // V' pack: destination index permuted within 8-word blocks
    uint32_t* dst = g_Vb + ((long)b*GC_)*(L_/2) + (l0 >> 1);
    const float* vsrc = g_VTc + ((long)b*GC_)*L_ + l0;
    #pragma unroll
    for (int t = 0; t < 8; t++) {
        int u = tid + t*512;
        int c = u >> 7, l2 = u & 127;
        int l2p = (l2 & ~7) | ((l2 & 3) << 1) | ((l2 >> 2) & 1);
        float2 v = *(const float2*)(vsrc + (long)c*L_ + 2*l2);
        dst[(long)c*(L_/2) + l2p] =
            pk_h2(v.y * dinvS[2*l2 + 1], v.x * dinvS[2*l2]);
    }
}

// ===========================================================================
// Kernel 4: final, 512 threads, 256-l tiles (16 iterations), dynamic smem.
// Fragment-order layouts (K: LDS.128, V: LDS.64), software-pipelined exp.
// ===========================================================================
#define KP 16
#define VP 136
#define VB_OFF (2*256*KP)
#define WB_OFF (VB_OFF + 2*32*VP)
#define FN_WORDS (WB_OFF + 32*17)    // 16896 + 544 = 17440 words (~70 KB)
#define MP 34

__global__ __launch_bounds__(512, 1) void k_final_mma(
    const float* __restrict__ graph, const float* __restrict__ Wc,
    const float* __restrict__ bc, float* __restrict__ out)
{
    extern __shared__ __align__(16) uint32_t SH[];
    uint32_t* Wb = SH + WB_OFF;
    int tid = threadIdx.x, w = tid >> 5, lane = tid & 31;
    int wp = w & 7, wh = w >> 3;
    int q = lane & 3, g = lane >> 2;
    int b = blockIdx.x >> 4, n0 = (blockIdx.x & 15) * 256;
    uint32_t sh_b = smem_u32(SH);

    uint32_t A[2][2][4];
    #pragma unroll
    for (int mt = 0; mt < 2; mt++) {
        const uint32_t* qp = g_Qb + ((long)b*N_ + n0 + wp*32 + mt*16)*16;
        #pragma unroll
        for (int kk = 0; kk < 2; kk++) {
            A[mt][kk][0] = qp[ g   *16 + 4*q + 2*kk    ];
            A[mt][kk][1] = qp[(g+8)*16 + 4*q + 2*kk    ];
            A[mt][kk][2] = qp[ g   *16 + 4*q + 2*kk + 1];
            A[mt][kk][3] = qp[(g+8)*16 + 4*q + 2*kk + 1];
        }
    }
    for (int i = tid; i < 32*16; i += 512) {
        int o = i >> 4, c2 = i & 15;
        Wb[o*17 + c2] = pk_h2(Wc[o*32 + 2*c2 + 1], Wc[o*32 + 2*c2]);
    }

    const uint32_t* vbsrc = g_Vb + ((long)b*GC_)*(L_/2);
    auto prefetch = [&](int lc, int buf) {
        const uint32_t* ksrc = g_Kb + ((long)b*L_ + lc*256)*16;
        #pragma unroll
        for (int it = 0; it < 2; it++) {
            int u = tid + it*512;
            int r = u >> 2, t = u & 3;
            cp16(sh_b + (buf*256*KP + r*KP + 4*t)*4, ksrc + r*16 + 4*t);
        }
        #pragma unroll
        for (int it = 0; it < 2; it++) {
            int u = tid + it*512;
            int c = u >> 5, t2 = u & 31;
            cp16(sh_b + (VB_OFF + buf*32*VP + c*VP + 4*t2)*4,
                 vbsrc + (long)c*(L_/2) + lc*128 + 4*t2);
        }
        CP_COMMIT();
    };
    prefetch(0, 0);

    float mc[2][4][4];
    #pragma unroll
    for (int mt = 0; mt < 2; mt++)
        #pragma unroll
        for (int cf = 0; cf < 4; cf++)
            #pragma unroll
            for (int x = 0; x < 4; x++) mc[mt][cf][x] = 0.f;

    int s0 = wh * 8;
    for (int lc = 0; lc < 16; lc++) {
        if (lc < 15) { prefetch(lc + 1, (lc + 1) & 1); CP_WAIT1(); }
        else CP_WAIT0();
        __syncthreads();
        const uint32_t* K = SH + (lc & 1)*256*KP;
        const uint32_t* V = SH + VB_OFF + (lc & 1)*32*VP;

        uint32_t A2p[2][4];   // exp fragments of previous ss
        #pragma unroll
        for (int ss = 0; ss < 8; ss++) {
            int s = s0 + ss;
            uint4 fa = *(const uint4*)&K[(g + 16*s    )*KP + 4*q];
            uint4 fb = *(const uint4*)&K[(g + 16*s + 8)*KP + 4*q];
            float c[2][2][4];
            #pragma unroll
            for (int mt = 0; mt < 2; mt++) {
                #pragma unroll
                for (int h = 0; h < 2; h++)
                    #pragma unroll
                    for (int x = 0; x < 4; x++) c[mt][h][x] = 0.f;
                mma_f16(c[mt][0], A[mt][0], fa.x, fa.y);
                mma_f16(c[mt][0], A[mt][1], fa.z, fa.w);
                mma_f16(c[mt][1], A[mt][0], fb.x, fb.y);
                mma_f16(c[mt][1], A[mt][1], fb.z, fb.w);
            }
            if (ss > 0) {   // GEMM2 for previous ss (A2p ready, no MUFU wait)
                int sp = s - 1;
                #pragma unroll
                for (int cf = 0; cf < 4; cf++) {
                    uint2 vv = *(const uint2*)&V[(g + 8*cf)*VP + 8*sp + 2*q];
                    #pragma unroll
                    for (int mt = 0; mt < 2; mt++)
                        mma_f16(mc[mt][cf], A2p[mt], vv.x, vv.y);
                }
            }
            #pragma unroll
            for (int mt = 0; mt < 2; mt++) {
                A2p[mt][0] = ex2h2(pk_h2(c[mt][0][1], c[mt][0][0]));
                A2p[mt][1] = ex2h2(pk_h2(c[mt][0][3], c[mt][0][2]));
                A2p[mt][2] = ex2h2(pk_h2(c[mt][1][1], c[mt][1][0]));
                A2p[mt][3] = ex2h2(pk_h2(c[mt][1][3], c[mt][1][2]));
            }
        }
        {   // flush GEMM2 for last ss of this lc (V buffer still live)
            int sp = s0 + 7;
            #pragma unroll
            for (int cf = 0; cf < 4; cf++) {
                uint2 vv = *(const uint2*)&V[(g + 8*cf)*VP + 8*sp + 2*q];
                #pragma unroll
                for (int mt = 0; mt < 2; mt++)
                    mma_f16(mc[mt][cf], A2p[mt], vv.x, vv.y);
            }
        }
        __syncthreads();
    }

    // combine warp-pair partials via smem (reuse SH as msgP[256][MP])
    float* msgP = (float*)SH;
    if (wh == 1) {
        #pragma unroll
        for (int mt = 0; mt < 2; mt++) {
            int rb = wp*32 + mt*16;
            #pragma unroll
            for (int cf = 0; cf < 4; cf++) {
                int col = cf*8 + 2*q;
                *(float2*)&msgP[(rb + g    )*MP + col] =
                    make_float2(mc[mt][cf][0], mc[mt][cf][1]);
                *(float2*)&msgP[(rb + g + 8)*MP + col] =
                    make_float2(mc[mt][cf][2], mc[mt][cf][3]);
            }
        }
    }
    __syncthreads();

    if (wh == 0) {
        #pragma unroll
        for (int mt = 0; mt < 2; mt++) {
            int rb = wp*32 + mt*16;
            #pragma unroll
            for (int cf = 0; cf < 4; cf++) {
                int col = cf*8 + 2*q;
                float2 p0 = *(const float2*)&msgP[(rb + g    )*MP + col];
                float2 p1 = *(const float2*)&msgP[(rb + g + 8)*MP + col];
                mc[mt][cf][0] += p0.x; mc[mt][cf][1] += p0.y;
                mc[mt][cf][2] += p1.x; mc[mt][cf][3] += p1.y;
            }
        }
        #pragma unroll
        for (int mt = 0; mt < 2; mt++) {
            uint32_t A3[2][4];
            #pragma unroll
            for (int t = 0; t < 2; t++) {
                A3[t][0] = pk_h2(mc[mt][2*t  ][1], mc[mt][2*t  ][0]);
                A3[t][1] = pk_h2(mc[mt][2*t  ][3], mc[mt][2*t  ][2]);
                A3[t][2] = pk_h2(mc[mt][2*t+1][1], mc[mt][2*t+1][0]);
                A3[t][3] = pk_h2(mc[mt][2*t+1][3], mc[mt][2*t+1][2]);
            }
            long nbase = (long)b*N_ + n0 + wp*32 + mt*16;
            const float* gp = graph + nbase*32;
            float* op = out + nbase*32;
            #pragma unroll
            for (int of = 0; of < 4; of++) {
                int col = 8*of + 2*q;
                float bc0 = bc[col], bc1 = bc[col + 1];
                float2 gr0 = *(const float2*)(gp + g*32 + col);
                float2 gr1 = *(const float2*)(gp + (g + 8)*32 + col);
                float c[4] = { gr0.x + bc0, gr0.y + bc1, gr1.x + bc0, gr1.y + bc1 };
                #pragma unroll
                for (int t = 0; t < 2; t++) {
                    uint32_t b0 = Wb[(g + 8*of)*17 + 8*t + q    ];
                    uint32_t b1 = Wb[(g + 8*of)*17 + 8*t + q + 4];
                    mma_f16(c, A3[t], b0, b1);
                }
                *(float2*)(op + g*32 + col)       = make_float2(c[0], c[1]);
                *(float2*)(op + (g + 8)*32 + col) = make_float2(c[2], c[3]);
            }
        }
    }
}

// ===========================================================================
extern "C" void kernel_launch(void* const* d_in, const int* in_sizes, int n_in,
                              void* d_out, int out_size)
{
    const float* graph = (const float*)d_in[0];
    const float* img   = (const float*)d_in[1];
    const float* Wq    = (const float*)d_in[2];
    const float* bq    = (const float*)d_in[3];
    const float* Wk    = (const float*)d_in[4];
    const float* bk    = (const float*)d_in[5];
    const float* Wv    = (const float*)d_in[6];
    const float* bv    = (const float*)d_in[7];
    const float* Wc    = (const float*)d_in[8];
    const float* bc    = (const float*)d_in[9];
    float* out = (float*)d_out;

    size_t proj_smem = (64*PW + 2*64*PI) * sizeof(uint32_t);
    size_t fin_smem  = FN_WORDS * sizeof(uint32_t);
    static int attr_set = 0;
    if (!attr_set) {
        cudaFuncSetAttribute(k_proj_kv_mma,
                             cudaFuncAttributeMaxDynamicSharedMemorySize,
                             (int)proj_smem);
        cudaFuncSetAttribute(k_final_mma,
                             cudaFuncAttributeMaxDynamicSharedMemorySize,
                             (int)fin_smem);
        attr_set = 1;
    }

    k_proj_q     <<<B_*(N_/64), 256>>>(graph, Wq, bq);
    k_proj_kv_mma<<<B_*(L_/256), 256, proj_smem>>>(img, Wk, bk, Wv, bv);
    k_stats_mma  <<<B_*(L_/256), 512>>>();
    k_final_mma  <<<B_*(N_/256), 512, fin_smem>>>(graph, Wc, bc, out);
}

// round 15
// speedup vs baseline: 1.3381x; 1.0172x over previous
#include <cuda_runtime.h>
#include <cstdint>

#define B_  8
#define N_  4096
#define L_  4096
#define GC_ 32
#define IC_ 256

// K/Q rows stored in fragment order: word w -> perm16(w) = ((w&3)<<2)|(w>>2)
// V' pairs stored with in-block perm: j -> ((j&3)<<1)|((j>>2)&1)
__device__ uint32_t g_Qb [B_*N_*16];      // [b][n][w'] f16x2 (Q*QSCALE)
__device__ uint32_t g_Kb [B_*L_*16];      // [b][l][w'] f16x2
__device__ float    g_VTc[B_*GC_*L_];     // [b][c][l] raw f32 (channel-major)
__device__ uint32_t g_Vb [B_*GC_*(L_/2)]; // [b][c][l2'] f16x2 of V*Dinv

#define QSCALE 0.2550668292560464f  // (1/sqrt(32)) * log2(e)

// ===========================================================================
// helpers
// ===========================================================================
__device__ __forceinline__ uint32_t smem_u32(const void* p) {
    uint32_t a;
    asm("{ .reg .u64 t; cvta.to.shared.u64 t, %1; cvt.u32.u64 %0, t; }"
        : "=r"(a) : "l"(p));
    return a;
}
__device__ __forceinline__ uint32_t pk_h2(float hi, float lo) {
    uint32_t r;
    asm("cvt.rn.f16x2.f32 %0, %1, %2;" : "=r"(r) : "f"(hi), "f"(lo));
    return r;
}
__device__ __forceinline__ uint32_t ex2h2(uint32_t x) {
    uint32_t y;
    asm("ex2.approx.f16x2 %0, %1;" : "=r"(y) : "r"(x));
    return y;
}
__device__ __forceinline__ uint32_t hadd2(uint32_t a, uint32_t b) {
    uint32_t r;
    asm("add.rn.f16x2 %0, %1, %2;" : "=r"(r) : "r"(a), "r"(b));
    return r;
}
__device__ __forceinline__ float hsum2f(uint32_t h2) {
    float lo, hi;
    asm("{ .reg .b16 l, h;\n\t mov.b32 {l, h}, %2;\n\t"
        "cvt.f32.f16 %0, l;\n\t cvt.f32.f16 %1, h; }"
        : "=f"(lo), "=f"(hi) : "r"(h2));
    return lo + hi;
}
// f32-accumulate MMA
__device__ __forceinline__ void mma_f16(float c[4], const uint32_t a[4],
                                        uint32_t b0, uint32_t b1) {
    asm volatile("mma.sync.aligned.m16n8k16.row.col.f32.f16.f16.f32 "
        "{%0,%1,%2,%3}, {%4,%5,%6,%7}, {%8,%9}, {%0,%1,%2,%3};"
        : "+f"(c[0]), "+f"(c[1]), "+f"(c[2]), "+f"(c[3])
        : "r"(a[0]), "r"(a[1]), "r"(a[2]), "r"(a[3]), "r"(b0), "r"(b1));
}
// f16-accumulate MMA: D packs {row g: (2q, 2q+1)} in d[0], {row g+8: ...} in d[1]
__device__ __forceinline__ void mma_f16d(uint32_t d[2], const uint32_t a[4],
                                         uint32_t b0, uint32_t b1) {
    asm volatile("mma.sync.aligned.m16n8k16.row.col.f16.f16.f16.f16 "
        "{%0,%1}, {%2,%3,%4,%5}, {%6,%7}, {%0,%1};"
        : "+r"(d[0]), "+r"(d[1])
        : "r"(a[0]), "r"(a[1]), "r"(a[2]), "r"(a[3]), "r"(b0), "r"(b1));
}
__device__ __forceinline__ void cp16(uint32_t s, const void* g) {
    asm volatile("cp.async.ca.shared.global [%0], [%1], 16;"
                 :: "r"(s), "l"(g) : "memory");
}
#define CP_COMMIT() asm volatile("cp.async.commit_group;" ::: "memory")
#define CP_WAIT1()  asm volatile("cp.async.wait_group 1;" ::: "memory")
#define CP_WAIT0()  asm volatile("cp.async.wait_group 0;" ::: "memory")

// ===========================================================================
// Kernel 1: Q projection -> f16x2, QSCALE folded, fragment-order layout
// ===========================================================================
__global__ __launch_bounds__(256) void k_proj_q(
    const float* __restrict__ graph, const float* __restrict__ Wq,
    const float* __restrict__ bq)
{
    __shared__ float WqS[GC_*33];
    __shared__ float gS[64*GC_];
    int b  = blockIdx.x >> 6;
    int n0 = (blockIdx.x & 63) * 64;
    int tid = threadIdx.x;

    for (int i = tid; i < GC_*GC_; i += 256)
        WqS[(i>>5)*33 + (i&31)] = Wq[i];
    const float* gp = graph + ((long)b*N_ + n0)*GC_;
    for (int i = tid; i < 64*GC_; i += 256) gS[i] = gp[i];
    __syncthreads();

    int o2 = tid & 15, nb = tid >> 4;
    int po2 = ((o2 & 3) << 2) | (o2 >> 2);   // perm16
    float b0 = bq[2*o2], b1 = bq[2*o2 + 1];
    #pragma unroll
    for (int j = 0; j < 4; j++) {
        int n = nb + 16*j;
        float a0 = b0, a1 = b1;
        #pragma unroll
        for (int c = 0; c < 32; c++) {
            float gv = gS[n*32 + c];
            a0 += WqS[(2*o2    )*33 + c] * gv;
            a1 += WqS[(2*o2 + 1)*33 + c] * gv;
        }
        g_Qb[((long)b*N_ + n0 + n)*16 + po2] = pk_h2(a1*QSCALE, a0*QSCALE);
    }
}

// ===========================================================================
// Kernel 2: K/V projection via f16 MMA. K stored fragment-order.
// ===========================================================================
#define PW 132
#define PI 260

__global__ __launch_bounds__(256, 1) void k_proj_kv_mma(
    const float* __restrict__ img,
    const float* __restrict__ Wk, const float* __restrict__ bk,
    const float* __restrict__ Wv, const float* __restrict__ bv)
{
    extern __shared__ uint32_t shm[];
    uint32_t* Wsm  = shm;
    float*    img0 = (float*)(shm + 64*PW);
    float*    img1 = img0 + 64*PI;

    int tid = threadIdx.x, w = tid >> 5, lane = tid & 31;
    int q = lane & 3, g = lane >> 2;
    int b = blockIdx.x >> 4, l0 = (blockIdx.x & 15) * 256;

    #pragma unroll
    for (int t = 0; t < 32; t++) {
        int u = tid + t*256;
        int o = u >> 7, c2 = u & 127;
        const float* src = (o < 32) ? (Wk + o*IC_ + 2*c2) : (Wv + (o-32)*IC_ + 2*c2);
        float2 v = *(const float2*)src;
        Wsm[o*PW + c2] = pk_h2(v.y, v.x);
    }

    auto pref = [&](int ks, float* dstbuf) {
        const float* src = img + ((long)b*IC_ + ks*64)*L_ + l0;
        uint32_t dstb = smem_u32(dstbuf);
        #pragma unroll
        for (int t = 0; t < 16; t++) {
            int u = tid + t*256;
            int c = u >> 6, col = (u & 63) * 4;
            cp16(dstb + (c*PI + col)*4, src + (long)c*L_ + col);
        }
        CP_COMMIT();
    };
    pref(0, img0);

    float C[4][4][4];
    #pragma unroll
    for (int mt = 0; mt < 4; mt++) {
        const float* bias = (mt < 2) ? bk : bv;
        int ob = (mt & 1) * 16;
        float blo = bias[ob + g], bhi = bias[ob + 8 + g];
        #pragma unroll
        for (int nt = 0; nt < 4; nt++) {
            C[mt][nt][0] = C[mt][nt][1] = blo;
            C[mt][nt][2] = C[mt][nt][3] = bhi;
        }
    }
    __syncthreads();

    int lw = w * 32;
    for (int ks = 0; ks < 4; ks++) {
        if (ks < 3) { pref(ks + 1, (ks & 1) ? img0 : img1); CP_WAIT1(); }
        else CP_WAIT0();
        __syncthreads();
        const float* I = (ks & 1) ? img1 : img0;
        #pragma unroll
        for (int kk = 0; kk < 4; kk++) {
            uint32_t A[4][4];
            #pragma unroll
            for (int mt = 0; mt < 4; mt++) {
                const uint32_t* wp = Wsm + (mt*16)*PW + ks*32 + kk*8;
                A[mt][0] = wp[ g   *PW + q];
                A[mt][1] = wp[(g+8)*PW + q];
                A[mt][2] = wp[ g   *PW + q + 4];
                A[mt][3] = wp[(g+8)*PW + q + 4];
            }
            uint32_t Bf[4][2];
            #pragma unroll
            for (int nt = 0; nt < 4; nt++) {
                int l = lw + nt*8 + g;
                const float* r0 = I + (kk*16 + 2*q    )*PI + l;
                const float* r1 = I + (kk*16 + 2*q + 8)*PI + l;
                Bf[nt][0] = pk_h2(r0[PI], r0[0]);
                Bf[nt][1] = pk_h2(r1[PI], r1[0]);
            }
            #pragma unroll
            for (int mt = 0; mt < 4; mt++)
                #pragma unroll
                for (int nt = 0; nt < 4; nt++)
                    mma_f16(C[mt][nt], A[mt], Bf[nt][0], Bf[nt][1]);
        }
        __syncthreads();
    }

    // K epilogue: quad shfl-transpose -> g_Kb[l][w'] (fragment-order)
    bool odd = (g & 1);
    int sA = 8*q + (g >> 1), sB = sA + 4;
    #pragma unroll
    for (int mt = 0; mt < 2; mt++)
        #pragma unroll
        for (int nt = 0; nt < 4; nt++) {
            float* c = C[mt][nt];
            float t0 = __shfl_sync(~0u, c[0], sA), t1 = __shfl_sync(~0u, c[1], sA);
            float t2 = __shfl_sync(~0u, c[0], sB), t3 = __shfl_sync(~0u, c[1], sB);
            float t4 = __shfl_sync(~0u, c[2], sA), t5 = __shfl_sync(~0u, c[3], sA);
            float t6 = __shfl_sync(~0u, c[2], sB), t7 = __shfl_sync(~0u, c[3], sB);
            float lo0 = odd ? t1 : t0, hi0 = odd ? t3 : t2;
            float lo1 = odd ? t5 : t4, hi1 = odd ? t7 : t6;
            long l = (long)b*L_ + l0 + lw + nt*8 + g;
            g_Kb[l*16 + 4*q + 2*mt    ] = pk_h2(hi0, lo0);
            g_Kb[l*16 + 4*q + 2*mt + 1] = pk_h2(hi1, lo1);
        }
    #pragma unroll
    for (int mt = 2; mt < 4; mt++)
        #pragma unroll
        for (int nt = 0; nt < 4; nt++) {
            int c = (mt - 2)*16 + g;
            long base = ((long)b*GC_ + c)*L_ + l0 + lw + nt*8 + 2*q;
            *(float2*)(g_VTc + base)         = make_float2(C[mt][nt][0], C[mt][nt][1]);
            *(float2*)(g_VTc + base + 8*L_)  = make_float2(C[mt][nt][2], C[mt][nt][3]);
        }
}

// ===========================================================================
// Kernel 3: stats, 512 threads, 256-n tiles. f16-accumulate GEMM1:
// D regs pack exp args directly -> ex2h2 -> hadd2.
// ===========================================================================
__global__ __launch_bounds__(512, 1) void k_stats_mma()
{
    __shared__ __align__(16) uint32_t Qs[2][256*16];
    __shared__ float dS[2][256];
    __shared__ float dinvS[256];
    int tid = threadIdx.x, w = tid >> 5, lane = tid & 31;
    int wp = w & 7, wh = w >> 3;
    int q = lane & 3, g = lane >> 2;
    int b = blockIdx.x >> 4, l0 = (blockIdx.x & 15) * 256;
    uint32_t qs_b = smem_u32(Qs);

    uint32_t A[2][2][4];
    #pragma unroll
    for (int mt = 0; mt < 2; mt++) {
        const uint32_t* kp = g_Kb + ((long)b*L_ + l0 + wp*32 + mt*16)*16;
        #pragma unroll
        for (int kk = 0; kk < 2; kk++) {
            A[mt][kk][0] = kp[ g   *16 + 4*q + 2*kk    ];
            A[mt][kk][1] = kp[(g+8)*16 + 4*q + 2*kk    ];
            A[mt][kk][2] = kp[ g   *16 + 4*q + 2*kk + 1];
            A[mt][kk][3] = kp[(g+8)*16 + 4*q + 2*kk + 1];
        }
    }

    auto prefetch = [&](int nc, int buf) {
        const uint32_t* src = g_Qb + ((long)b*N_ + nc*256)*16;
        #pragma unroll
        for (int it = 0; it < 2; it++) {
            int u = tid + it*512;
            int r = u >> 2, t = u & 3;
            cp16(qs_b + (buf*256*16 + r*16 + 4*t)*4, src + r*16 + 4*t);
        }
        CP_COMMIT();
    };
    prefetch(0, 0);

    float d[2][2] = {{0.f,0.f},{0.f,0.f}};
    int j0 = wh * 16;
    for (int nc = 0; nc < 16; nc++) {
        if (nc < 15) { prefetch(nc + 1, (nc + 1) & 1); CP_WAIT1(); }
        else CP_WAIT0();
        __syncthreads();
        const uint32_t* Q = &Qs[nc & 1][0];
        uint32_t dh[2][2] = {{0u,0u},{0u,0u}};
        #pragma unroll 4
        for (int jj = 0; jj < 16; jj++) {
            int j = j0 + jj;
            uint4 f = *(const uint4*)&Q[(g + 8*j)*16 + 4*q];
            #pragma unroll
            for (int mt = 0; mt < 2; mt++) {
                uint32_t dd[2] = {0u, 0u};
                mma_f16d(dd, A[mt][0], f.x, f.y);
                mma_f16d(dd, A[mt][1], f.z, f.w);
                dh[mt][0] = hadd2(dh[mt][0], ex2h2(dd[0]));
                dh[mt][1] = hadd2(dh[mt][1], ex2h2(dd[1]));
            }
        }
        #pragma unroll
        for (int mt = 0; mt < 2; mt++) {
            d[mt][0] += hsum2f(dh[mt][0]);
            d[mt][1] += hsum2f(dh[mt][1]);
        }
        __syncthreads();
    }
    #pragma unroll
    for (int mt = 0; mt < 2; mt++) {
        #pragma unroll
        for (int h = 0; h < 2; h++) {
            float dv = d[mt][h];
            dv += __shfl_xor_sync(~0u, dv, 1);
            dv += __shfl_xor_sync(~0u, dv, 2);
            if (q == 0) dS[wh][wp*32 + mt*16 + h*8 + g] = dv;
        }
    }
    __syncthreads();
    if (tid < 256) dinvS[tid] = 1.0f / (dS[0][tid] + dS[1][tid]);
    __syncthreads();

    // V' pack: destination index permuted within 8-word blocks
    uint32_t* dst = g_Vb + ((long)b*GC_)*(L_/2) + (l0 >> 1);
    const float* vsrc = g_VTc + ((long)b*GC_)*L_ + l0;
    #pragma unroll
    for (int t = 0; t < 8; t++) {
        int u = tid + t*512;
        int c = u >> 7, l2 = u & 127;
        int l2p = (l2 & ~7) | ((l2 & 3) << 1) | ((l2 >> 2) & 1);
        float2 v = *(const float2*)(vsrc + (long)c*L_ + 2*l2);
        dst[(long)c*(L_/2) + l2p] =
            pk_h2(v.y * dinvS[2*l2 + 1], v.x * dinvS[2*l2]);
    }
}

// ===========================================================================
// Kernel 4: final, 512 threads, 256-l tiles, dynamic smem.
// f16-accumulate GEMM1 -> ex2h2 directly on D regs -> GEMM2 A operand.
// Software-pipelined: GEMM2(ss-1) overlaps GEMM1(ss).
// ===========================================================================
#define KP 16
#define VP 136
#define VB_OFF (2*256*KP)
#define WB_OFF (VB_OFF + 2*32*VP)
#define FN_WORDS (WB_OFF + 32*17)
#define MP 34

__global__ __launch_bounds__(512, 1) void k_final_mma(
    const float* __restrict__ graph, const float* __restrict__ Wc,
    const float* __restrict__ bc, float* __restrict__ out)
{
    extern __shared__ __align__(16) uint32_t SH[];
    uint32_t* Wb = SH + WB_OFF;
    int tid = threadIdx.x, w = tid >> 5, lane = tid & 31;
    int wp = w & 7, wh = w >> 3;
    int q = lane & 3, g = lane >> 2;
    int b = blockIdx.x >> 4, n0 = (blockIdx.x & 15) * 256;
    uint32_t sh_b = smem_u32(SH);

    uint32_t A[2][2][4];
    #pragma unroll
    for (int mt = 0; mt < 2; mt++) {
        const uint32_t* qp = g_Qb + ((long)b*N_ + n0 + wp*32 + mt*16)*16;
        #pragma unroll
        for (int kk = 0; kk < 2; kk++) {
            A[mt][kk][0] = qp[ g   *16 + 4*q + 2*kk    ];
            A[mt][kk][1] = qp[(g+8)*16 + 4*q + 2*kk    ];
            A[mt][kk][2] = qp[ g   *16 + 4*q + 2*kk + 1];
            A[mt][kk][3] = qp[(g+8)*16 + 4*q + 2*kk + 1];
        }
    }
    for (int i = tid; i < 32*16; i += 512) {
        int o = i >> 4, c2 = i & 15;
        Wb[o*17 + c2] = pk_h2(Wc[o*32 + 2*c2 + 1], Wc[o*32 + 2*c2]);
    }

    const uint32_t* vbsrc = g_Vb + ((long)b*GC_)*(L_/2);
    auto prefetch = [&](int lc, int buf) {
        const uint32_t* ksrc = g_Kb + ((long)b*L_ + lc*256)*16;
        #pragma unroll
        for (int it = 0; it < 2; it++) {
            int u = tid + it*512;
            int r = u >> 2, t = u & 3;
            cp16(sh_b + (buf*256*KP + r*KP + 4*t)*4, ksrc + r*16 + 4*t);
        }
        #pragma unroll
        for (int it = 0; it < 2; it++) {
            int u = tid + it*512;
            int c = u >> 5, t2 = u & 31;
            cp16(sh_b + (VB_OFF + buf*32*VP + c*VP + 4*t2)*4,
                 vbsrc + (long)c*(L_/2) + lc*128 + 4*t2);
        }
        CP_COMMIT();
    };
    prefetch(0, 0);

    float mc[2][4][4];
    #pragma unroll
    for (int mt = 0; mt < 2; mt++)
        #pragma unroll
        for (int cf = 0; cf < 4; cf++)
            #pragma unroll
            for (int x = 0; x < 4; x++) mc[mt][cf][x] = 0.f;

    int s0 = wh * 8;
    for (int lc = 0; lc < 16; lc++) {
        if (lc < 15) { prefetch(lc + 1, (lc + 1) & 1); CP_WAIT1(); }
        else CP_WAIT0();
        __syncthreads();
        const uint32_t* K = SH + (lc & 1)*256*KP;
        const uint32_t* V = SH + VB_OFF + (lc & 1)*32*VP;

        uint32_t A2p[2][4];   // exp fragments of previous ss
        #pragma unroll
        for (int ss = 0; ss < 8; ss++) {
            int s = s0 + ss;
            uint4 fa = *(const uint4*)&K[(g + 16*s    )*KP + 4*q];
            uint4 fb = *(const uint4*)&K[(g + 16*s + 8)*KP + 4*q];
            uint32_t da[2][2], db[2][2];
            #pragma unroll
            for (int mt = 0; mt < 2; mt++) {
                da[mt][0] = da[mt][1] = 0u;
                db[mt][0] = db[mt][1] = 0u;
                mma_f16d(da[mt], A[mt][0], fa.x, fa.y);
                mma_f16d(da[mt], A[mt][1], fa.z, fa.w);
                mma_f16d(db[mt], A[mt][0], fb.x, fb.y);
                mma_f16d(db[mt], A[mt][1], fb.z, fb.w);
            }
            if (ss > 0) {   // GEMM2 for previous ss (A2p ready)
                int sp = s - 1;
                #pragma unroll
                for (int cf = 0; cf < 4; cf++) {
                    uint2 vv = *(const uint2*)&V[(g + 8*cf)*VP + 8*sp + 2*q];
                    #pragma unroll
                    for (int mt = 0; mt < 2; mt++)
                        mma_f16(mc[mt][cf], A2p[mt], vv.x, vv.y);
                }
            }
            #pragma unroll
            for (int mt = 0; mt < 2; mt++) {
                A2p[mt][0] = ex2h2(da[mt][0]);
                A2p[mt][1] = ex2h2(da[mt][1]);
                A2p[mt][2] = ex2h2(db[mt][0]);
                A2p[mt][3] = ex2h2(db[mt][1]);
            }
        }
        {   // flush GEMM2 for last ss of this lc
            int sp = s0 + 7;
            #pragma unroll
            for (int cf = 0; cf < 4; cf++) {
                uint2 vv = *(const uint2*)&V[(g + 8*cf)*VP + 8*sp + 2*q];
                #pragma unroll
                for (int mt = 0; mt < 2; mt++)
                    mma_f16(mc[mt][cf], A2p[mt], vv.x, vv.y);
            }
        }
        __syncthreads();
    }

    // combine warp-pair partials via smem (reuse SH as msgP[256][MP])
    float* msgP = (float*)SH;
    if (wh == 1) {
        #pragma unroll
        for (int mt = 0; mt < 2; mt++) {
            int rb = wp*32 + mt*16;
            #pragma unroll
            for (int cf = 0; cf < 4; cf++) {
                int col = cf*8 + 2*q;
                *(float2*)&msgP[(rb + g    )*MP + col] =
                    make_float2(mc[mt][cf][0], mc[mt][cf][1]);
                *(float2*)&msgP[(rb + g + 8)*MP + col] =
                    make_float2(mc[mt][cf][2], mc[mt][cf][3]);
            }
        }
    }
    __syncthreads();

    if (wh == 0) {
        #pragma unroll
        for (int mt = 0; mt < 2; mt++) {
            int rb = wp*32 + mt*16;
            #pragma unroll
            for (int cf = 0; cf < 4; cf++) {
                int col = cf*8 + 2*q;
                float2 p0 = *(const float2*)&msgP[(rb + g    )*MP + col];
                float2 p1 = *(const float2*)&msgP[(rb + g + 8)*MP + col];
                mc[mt][cf][0] += p0.x; mc[mt][cf][1] += p0.y;
                mc[mt][cf][2] += p1.x; mc[mt][cf][3] += p1.y;
            }
        }
        #pragma unroll
        for (int mt = 0; mt < 2; mt++) {
            uint32_t A3[2][4];
            #pragma unroll
            for (int t = 0; t < 2; t++) {
                A3[t][0] = pk_h2(mc[mt][2*t  ][1], mc[mt][2*t  ][0]);
                A3[t][1] = pk_h2(mc[mt][2*t  ][3], mc[mt][2*t  ][2]);
                A3[t][2] = pk_h2(mc[mt][2*t+1][1], mc[mt][2*t+1][0]);
                A3[t][3] = pk_h2(mc[mt][2*t+1][3], mc[mt][2*t+1][2]);
            }
            long nbase = (long)b*N_ + n0 + wp*32 + mt*16;
            const float* gp = graph + nbase*32;
            float* op = out + nbase*32;
            #pragma unroll
            for (int of = 0; of < 4; of++) {
                int col = 8*of + 2*q;
                float bc0 = bc[col], bc1 = bc[col + 1];
                float2 gr0 = *(const float2*)(gp + g*32 + col);
                float2 gr1 = *(const float2*)(gp + (g + 8)*32 + col);
                float c[4] = { gr0.x + bc0, gr0.y + bc1, gr1.x + bc0, gr1.y + bc1 };
                #pragma unroll
                for (int t = 0; t < 2; t++) {
                    uint32_t b0 = Wb[(g + 8*of)*17 + 8*t + q    ];
                    uint32_t b1 = Wb[(g + 8*of)*17 + 8*t + q + 4];
                    mma_f16(c, A3[t], b0, b1);
                }
                *(float2*)(op + g*32 + col)       = make_float2(c[0], c[1]);
                *(float2*)(op + (g + 8)*32 + col) = make_float2(c[2], c[3]);
            }
        }
    }
}

// ===========================================================================
extern "C" void kernel_launch(void* const* d_in, const int* in_sizes, int n_in,
                              void* d_out, int out_size)
{
    const float* graph = (const float*)d_in[0];
    const float* img   = (const float*)d_in[1];
    const float* Wq    = (const float*)d_in[2];
    const float* bq    = (const float*)d_in[3];
    const float* Wk    = (const float*)d_in[4];
    const float* bk    = (const float*)d_in[5];
    const float* Wv    = (const float*)d_in[6];
    const float* bv    = (const float*)d_in[7];
    const float* Wc    = (const float*)d_in[8];
    const float* bc    = (const float*)d_in[9];
    float* out = (float*)d_out;

    size_t proj_smem = (64*PW + 2*64*PI) * sizeof(uint32_t);
    size_t fin_smem  = FN_WORDS * sizeof(uint32_t);
    static int attr_set = 0;
    if (!attr_set) {
        cudaFuncSetAttribute(k_proj_kv_mma,
                             cudaFuncAttributeMaxDynamicSharedMemorySize,
                             (int)proj_smem);
        cudaFuncSetAttribute(k_final_mma,
                             cudaFuncAttributeMaxDynamicSharedMemorySize,
                             (int)fin_smem);
        attr_set = 1;
    }

    k_proj_q     <<<B_*(N_/64), 256>>>(graph, Wq, bq);
    k_proj_kv_mma<<<B_*(L_/256), 256, proj_smem>>>(img, Wk, bk, Wv, bv);
    k_stats_mma  <<<B_*(L_/256), 512>>>();
    k_final_mma  <<<B_*(N_/256), 512, fin_smem>>>(graph, Wc, bc, out);
}

// round 16
// speedup vs baseline: 1.3722x; 1.0255x over previous
#include <cuda_runtime.h>
#include <cstdint>

#define B_  8
#define N_  4096
#define L_  4096
#define GC_ 32
#define IC_ 256

// K/Q rows stored in fragment order: word w -> perm16(w) = ((w&3)<<2)|(w>>2)
// V' pairs stored with in-block perm: j -> ((j&3)<<1)|((j>>2)&1)
__device__ uint32_t g_Qb [B_*N_*16];      // [b][n][w'] f16x2 (Q*QSCALE)
__device__ uint32_t g_Kb [B_*L_*16];      // [b][l][w'] f16x2
__device__ float    g_VTc[B_*GC_*L_];     // [b][c][l] raw f32 (channel-major)
__device__ uint32_t g_Vb [B_*GC_*(L_/2)]; // [b][c][l2'] f16x2 of V*Dinv

#define QSCALE 0.2550668292560464f  // (1/sqrt(32)) * log2(e)

// ===========================================================================
// helpers
// ===========================================================================
__device__ __forceinline__ uint32_t smem_u32(const void* p) {
    uint32_t a;
    asm("{ .reg .u64 t; cvta.to.shared.u64 t, %1; cvt.u32.u64 %0, t; }"
        : "=r"(a) : "l"(p));
    return a;
}
__device__ __forceinline__ uint32_t pk_h2(float hi, float lo) {
    uint32_t r;
    asm("cvt.rn.f16x2.f32 %0, %1, %2;" : "=r"(r) : "f"(hi), "f"(lo));
    return r;
}
__device__ __forceinline__ uint32_t ex2h2(uint32_t x) {
    uint32_t y;
    asm("ex2.approx.f16x2 %0, %1;" : "=r"(y) : "r"(x));
    return y;
}
__device__ __forceinline__ uint32_t hadd2(uint32_t a, uint32_t b) {
    uint32_t r;
    asm("add.rn.f16x2 %0, %1, %2;" : "=r"(r) : "r"(a), "r"(b));
    return r;
}
__device__ __forceinline__ float hsum2f(uint32_t h2) {
    float lo, hi;
    asm("{ .reg .b16 l, h;\n\t mov.b32 {l, h}, %2;\n\t"
        "cvt.f32.f16 %0, l;\n\t cvt.f32.f16 %1, h; }"
        : "=f"(lo), "=f"(hi) : "r"(h2));
    return lo + hi;
}
// f32-accumulate MMA
__device__ __forceinline__ void mma_f16(float c[4], const uint32_t a[4],
                                        uint32_t b0, uint32_t b1) {
    asm volatile("mma.sync.aligned.m16n8k16.row.col.f32.f16.f16.f32 "
        "{%0,%1,%2,%3}, {%4,%5,%6,%7}, {%8,%9}, {%0,%1,%2,%3};"
        : "+f"(c[0]), "+f"(c[1]), "+f"(c[2]), "+f"(c[3])
        : "r"(a[0]), "r"(a[1]), "r"(a[2]), "r"(a[3]), "r"(b0), "r"(b1));
}
// f16-accumulate MMA: D packs {row g: (2q, 2q+1)} in d[0], {row g+8: ...} in d[1]
__device__ __forceinline__ void mma_f16d(uint32_t d[2], const uint32_t a[4],
                                         uint32_t b0, uint32_t b1) {
    asm volatile("mma.sync.aligned.m16n8k16.row.col.f16.f16.f16.f16 "
        "{%0,%1}, {%2,%3,%4,%5}, {%6,%7}, {%0,%1};"
        : "+r"(d[0]), "+r"(d[1])
        : "r"(a[0]), "r"(a[1]), "r"(a[2]), "r"(a[3]), "r"(b0), "r"(b1));
}
__device__ __forceinline__ void cp16(uint32_t s, const void* g) {
    asm volatile("cp.async.ca.shared.global [%0], [%1], 16;"
                 :: "r"(s), "l"(g) : "memory");
}
#define CP_COMMIT() asm volatile("cp.async.commit_group;" ::: "memory")
#define CP_WAIT1()  asm volatile("cp.async.wait_group 1;" ::: "memory")
#define CP_WAIT0()  asm volatile("cp.async.wait_group 0;" ::: "memory")

// ===========================================================================
// Kernel 1: Q projection -> f16x2, QSCALE folded, fragment-order layout
// ===========================================================================
__global__ __launch_bounds__(256) void k_proj_q(
    const float* __restrict__ graph, const float* __restrict__ Wq,
    const float* __restrict__ bq)
{
    __shared__ float WqS[GC_*33];
    __shared__ float gS[64*GC_];
    int b  = blockIdx.x >> 6;
    int n0 = (blockIdx.x & 63) * 64;
    int tid = threadIdx.x;

    for (int i = tid; i < GC_*GC_; i += 256)
        WqS[(i>>5)*33 + (i&31)] = Wq[i];
    const float* gp = graph + ((long)b*N_ + n0)*GC_;
    for (int i = tid; i < 64*GC_; i += 256) gS[i] = gp[i];
    __syncthreads();

    int o2 = tid & 15, nb = tid >> 4;
    int po2 = ((o2 & 3) << 2) | (o2 >> 2);   // perm16
    float b0 = bq[2*o2], b1 = bq[2*o2 + 1];
    #pragma unroll
    for (int j = 0; j < 4; j++) {
        int n = nb + 16*j;
        float a0 = b0, a1 = b1;
        #pragma unroll
        for (int c = 0; c < 32; c++) {
            float gv = gS[n*32 + c];
            a0 += WqS[(2*o2    )*33 + c] * gv;
            a1 += WqS[(2*o2 + 1)*33 + c] * gv;
        }
        g_Qb[((long)b*N_ + n0 + n)*16 + po2] = pk_h2(a1*QSCALE, a0*QSCALE);
    }
}

// ===========================================================================
// Kernel 2: K/V projection via f16 MMA. K stored fragment-order.
// ===========================================================================
#define PW 132
#define PI 260

__global__ __launch_bounds__(256, 1) void k_proj_kv_mma(
    const float* __restrict__ img,
    const float* __restrict__ Wk, const float* __restrict__ bk,
    const float* __restrict__ Wv, const float* __restrict__ bv)
{
    extern __shared__ uint32_t shm[];
    uint32_t* Wsm  = shm;
    float*    img0 = (float*)(shm + 64*PW);
    float*    img1 = img0 + 64*PI;

    int tid = threadIdx.x, w = tid >> 5, lane = tid & 31;
    int q = lane & 3, g = lane >> 2;
    int b = blockIdx.x >> 4, l0 = (blockIdx.x & 15) * 256;

    #pragma unroll
    for (int t = 0; t < 32; t++) {
        int u = tid + t*256;
        int o = u >> 7, c2 = u & 127;
        const float* src = (o < 32) ? (Wk + o*IC_ + 2*c2) : (Wv + (o-32)*IC_ + 2*c2);
        float2 v = *(const float2*)src;
        Wsm[o*PW + c2] = pk_h2(v.y, v.x);
    }

    auto pref = [&](int ks, float* dstbuf) {
        const float* src = img + ((long)b*IC_ + ks*64)*L_ + l0;
        uint32_t dstb = smem_u32(dstbuf);
        #pragma unroll
        for (int t = 0; t < 16; t++) {
            int u = tid + t*256;
            int c = u >> 6, col = (u & 63) * 4;
            cp16(dstb + (c*PI + col)*4, src + (long)c*L_ + col);
        }
        CP_COMMIT();
    };
    pref(0, img0);

    float C[4][4][4];
    #pragma unroll
    for (int mt = 0; mt < 4; mt++) {
        const float* bias = (mt < 2) ? bk : bv;
        int ob = (mt & 1) * 16;
        float blo = bias[ob + g], bhi = bias[ob + 8 + g];
        #pragma unroll
        for (int nt = 0; nt < 4; nt++) {
            C[mt][nt][0] = C[mt][nt][1] = blo;
            C[mt][nt][2] = C[mt][nt][3] = bhi;
        }
    }
    __syncthreads();

    int lw = w * 32;
    for (int ks = 0; ks < 4; ks++) {
        if (ks < 3) { pref(ks + 1, (ks & 1) ? img0 : img1); CP_WAIT1(); }
        else CP_WAIT0();
        __syncthreads();
        const float* I = (ks & 1) ? img1 : img0;
        #pragma unroll
        for (int kk = 0; kk < 4; kk++) {
            uint32_t A[4][4];
            #pragma unroll
            for (int mt = 0; mt < 4; mt++) {
                const uint32_t* wp = Wsm + (mt*16)*PW + ks*32 + kk*8;
                A[mt][0] = wp[ g   *PW + q];
                A[mt][1] = wp[(g+8)*PW + q];
                A[mt][2] = wp[ g   *PW + q + 4];
                A[mt][3] = wp[(g+8)*PW + q + 4];
            }
            uint32_t Bf[4][2];
            #pragma unroll
            for (int nt = 0; nt < 4; nt++) {
                int l = lw + nt*8 + g;
                const float* r0 = I + (kk*16 + 2*q    )*PI + l;
                const float* r1 = I + (kk*16 + 2*q + 8)*PI + l;
                Bf[nt][0] = pk_h2(r0[PI], r0[0]);
                Bf[nt][1] = pk_h2(r1[PI], r1[0]);
            }
            #pragma unroll
            for (int mt = 0; mt < 4; mt++)
                #pragma unroll
                for (int nt = 0; nt < 4; nt++)
                    mma_f16(C[mt][nt], A[mt], Bf[nt][0], Bf[nt][1]);
        }
        __syncthreads();
    }

    // K epilogue: quad shfl-transpose -> g_Kb[l][w'] (fragment-order)
    bool odd = (g & 1);
    int sA = 8*q + (g >> 1), sB = sA + 4;
    #pragma unroll
    for (int mt = 0; mt < 2; mt++)
        #pragma unroll
        for (int nt = 0; nt < 4; nt++) {
            float* c = C[mt][nt];
            float t0 = __shfl_sync(~0u, c[0], sA), t1 = __shfl_sync(~0u, c[1], sA);
            float t2 = __shfl_sync(~0u, c[0], sB), t3 = __shfl_sync(~0u, c[1], sB);
            float t4 = __shfl_sync(~0u, c[2], sA), t5 = __shfl_sync(~0u, c[3], sA);
            float t6 = __shfl_sync(~0u, c[2], sB), t7 = __shfl_sync(~0u, c[3], sB);
            float lo0 = odd ? t1 : t0, hi0 = odd ? t3 : t2;
            float lo1 = odd ? t5 : t4, hi1 = odd ? t7 : t6;
            long l = (long)b*L_ + l0 + lw + nt*8 + g;
            g_Kb[l*16 + 4*q + 2*mt    ] = pk_h2(hi0, lo0);
            g_Kb[l*16 + 4*q + 2*mt + 1] = pk_h2(hi1, lo1);
        }
    #pragma unroll
    for (int mt = 2; mt < 4; mt++)
        #pragma unroll
        for (int nt = 0; nt < 4; nt++) {
            int c = (mt - 2)*16 + g;
            long base = ((long)b*GC_ + c)*L_ + l0 + lw + nt*8 + 2*q;
            *(float2*)(g_VTc + base)         = make_float2(C[mt][nt][0], C[mt][nt][1]);
            *(float2*)(g_VTc + base + 8*L_)  = make_float2(C[mt][nt][2], C[mt][nt][3]);
        }
}

// ===========================================================================
// Kernel 3: stats, 512 threads, 256-n tiles. f16-acc GEMM1 feeds ex2h2
// directly; exp/accumulate of step jj-1 overlaps MMAs of jj (1-stage pipe).
// ===========================================================================
__global__ __launch_bounds__(512, 1) void k_stats_mma()
{
    __shared__ __align__(16) uint32_t Qs[2][256*16];
    __shared__ float dS[2][256];
    __shared__ float dinvS[256];
    int tid = threadIdx.x, w = tid >> 5, lane = tid & 31;
    int wp = w & 7, wh = w >> 3;
    int q = lane & 3, g = lane >> 2;
    int b = blockIdx.x >> 4, l0 = (blockIdx.x & 15) * 256;
    uint32_t qs_b = smem_u32(Qs);

    uint32_t A[2][2][4];
    #pragma unroll
    for (int mt = 0; mt < 2; mt++) {
        const uint32_t* kp = g_Kb + ((long)b*L_ + l0 + wp*32 + mt*16)*16;
        #pragma unroll
        for (int kk = 0; kk < 2; kk++) {
            A[mt][kk][0] = kp[ g   *16 + 4*q + 2*kk    ];
            A[mt][kk][1] = kp[(g+8)*16 + 4*q + 2*kk    ];
            A[mt][kk][2] = kp[ g   *16 + 4*q + 2*kk + 1];
            A[mt][kk][3] = kp[(g+8)*16 + 4*q + 2*kk + 1];
        }
    }

    auto prefetch = [&](int nc, int buf) {
        const uint32_t* src = g_Qb + ((long)b*N_ + nc*256)*16;
        #pragma unroll
        for (int it = 0; it < 2; it++) {
            int u = tid + it*512;
            int r = u >> 2, t = u & 3;
            cp16(qs_b + (buf*256*16 + r*16 + 4*t)*4, src + r*16 + 4*t);
        }
        CP_COMMIT();
    };
    prefetch(0, 0);

    float d[2][2] = {{0.f,0.f},{0.f,0.f}};
    int j0 = wh * 16;
    for (int nc = 0; nc < 16; nc++) {
        if (nc < 15) { prefetch(nc + 1, (nc + 1) & 1); CP_WAIT1(); }
        else CP_WAIT0();
        __syncthreads();
        const uint32_t* Q = &Qs[nc & 1][0];
        uint32_t dh[2][2] = {{0u,0u},{0u,0u}};
        uint32_t ddp[2][2];   // previous step's GEMM1 results
        #pragma unroll 4
        for (int jj = 0; jj < 16; jj++) {
            int j = j0 + jj;
            uint4 f = *(const uint4*)&Q[(g + 8*j)*16 + 4*q];
            uint32_t dd[2][2];
            #pragma unroll
            for (int mt = 0; mt < 2; mt++) {
                dd[mt][0] = dd[mt][1] = 0u;
                mma_f16d(dd[mt], A[mt][0], f.x, f.y);
                mma_f16d(dd[mt], A[mt][1], f.z, f.w);
            }
            if (jj > 0) {   // exp/accumulate previous step (overlaps MMAs above)
                #pragma unroll
                for (int mt = 0; mt < 2; mt++) {
                    dh[mt][0] = hadd2(dh[mt][0], ex2h2(ddp[mt][0]));
                    dh[mt][1] = hadd2(dh[mt][1], ex2h2(ddp[mt][1]));
                }
            }
            #pragma unroll
            for (int mt = 0; mt < 2; mt++) {
                ddp[mt][0] = dd[mt][0];
                ddp[mt][1] = dd[mt][1];
            }
        }
        #pragma unroll
        for (int mt = 0; mt < 2; mt++) {   // flush last step
            dh[mt][0] = hadd2(dh[mt][0], ex2h2(ddp[mt][0]));
            dh[mt][1] = hadd2(dh[mt][1], ex2h2(ddp[mt][1]));
            d[mt][0] += hsum2f(dh[mt][0]);
            d[mt][1] += hsum2f(dh[mt][1]);
        }
        __syncthreads();
    }
    #pragma unroll
    for (int mt = 0; mt < 2; mt++) {
        #pragma unroll
        for (int h = 0; h < 2; h++) {
            float dv = d[mt][h];
            dv += __shfl_xor_sync(~0u, dv, 1);
            dv += __shfl_xor_sync(~0u, dv, 2);
            if (q == 0) dS[wh][wp*32 + mt*16 + h*8 + g] = dv;
        }
    }
    __syncthreads();
    if (tid < 256) dinvS[tid] = 1.0f / (dS[0][tid] + dS[1][tid]);
    __syncthreads();

    // V' pack: destination index permuted within 8-word blocks
    uint32_t* dst = g_Vb + ((long)b*GC_)*(L_/2) + (l0 >> 1);
    const float* vsrc = g_VTc + ((long)b*GC_)*L_ + l0;
    #pragma unroll
    for (int t = 0; t < 8; t++) {
        int u = tid + t*512;
        int c = u >> 7, l2 = u & 127;
        int l2p = (l2 & ~7) | ((l2 & 3) << 1) | ((l2 >> 2) & 1);
        float2 v = *(const float2*)(vsrc + (long)c*L_ + 2*l2);
        dst[(long)c*(L_/2) + l2p] =
            pk_h2(v.y * dinvS[2*l2 + 1], v.x * dinvS[2*l2]);
    }
}

// ===========================================================================
// Kernel 4: final, 512 threads, 256-l tiles, dynamic smem.
// f16-acc GEMM1 -> ex2h2 on D regs; 2-STAGE exp pipeline:
// GEMM2(ss) consumes A2 produced at ss-2.
// ===========================================================================
#define KP 16
#define VP 136
#define VB_OFF (2*256*KP)
#define WB_OFF (VB_OFF + 2*32*VP)
#define FN_WORDS (WB_OFF + 32*17)
#define MP 34

__global__ __launch_bounds__(512, 1) void k_final_mma(
    const float* __restrict__ graph, const float* __restrict__ Wc,
    const float* __restrict__ bc, float* __restrict__ out)
{
    extern __shared__ __align__(16) uint32_t SH[];
    uint32_t* Wb = SH + WB_OFF;
    int tid = threadIdx.x, w = tid >> 5, lane = tid & 31;
    int wp = w & 7, wh = w >> 3;
    int q = lane & 3, g = lane >> 2;
    int b = blockIdx.x >> 4, n0 = (blockIdx.x & 15) * 256;
    uint32_t sh_b = smem_u32(SH);

    uint32_t A[2][2][4];
    #pragma unroll
    for (int mt = 0; mt < 2; mt++) {
        const uint32_t* qp = g_Qb + ((long)b*N_ + n0 + wp*32 + mt*16)*16;
        #pragma unroll
        for (int kk = 0; kk < 2; kk++) {
            A[mt][kk][0] = qp[ g   *16 + 4*q + 2*kk    ];
            A[mt][kk][1] = qp[(g+8)*16 + 4*q + 2*kk    ];
            A[mt][kk][2] = qp[ g   *16 + 4*q + 2*kk + 1];
            A[mt][kk][3] = qp[(g+8)*16 + 4*q + 2*kk + 1];
        }
    }
    for (int i = tid; i < 32*16; i += 512) {
        int o = i >> 4, c2 = i & 15;
        Wb[o*17 + c2] = pk_h2(Wc[o*32 + 2*c2 + 1], Wc[o*32 + 2*c2]);
    }

    const uint32_t* vbsrc = g_Vb + ((long)b*GC_)*(L_/2);
    auto prefetch = [&](int lc, int buf) {
        const uint32_t* ksrc = g_Kb + ((long)b*L_ + lc*256)*16;
        #pragma unroll
        for (int it = 0; it < 2; it++) {
            int u = tid + it*512;
            int r = u >> 2, t = u & 3;
            cp16(sh_b + (buf*256*KP + r*KP + 4*t)*4, ksrc + r*16 + 4*t);
        }
        #pragma unroll
        for (int it = 0; it < 2; it++) {
            int u = tid + it*512;
            int c = u >> 5, t2 = u & 31;
            cp16(sh_b + (VB_OFF + buf*32*VP + c*VP + 4*t2)*4,
                 vbsrc + (long)c*(L_/2) + lc*128 + 4*t2);
        }
        CP_COMMIT();
    };
    prefetch(0, 0);

    float mc[2][4][4];
    #pragma unroll
    for (int mt = 0; mt < 2; mt++)
        #pragma unroll
        for (int cf = 0; cf < 4; cf++)
            #pragma unroll
            for (int x = 0; x < 4; x++) mc[mt][cf][x] = 0.f;

    int s0 = wh * 8;
    for (int lc = 0; lc < 16; lc++) {
        if (lc < 15) { prefetch(lc + 1, (lc + 1) & 1); CP_WAIT1(); }
        else CP_WAIT0();
        __syncthreads();
        const uint32_t* K = SH + (lc & 1)*256*KP;
        const uint32_t* V = SH + VB_OFF + (lc & 1)*32*VP;

        uint32_t A2p[2][2][4];   // 2-slot exp pipeline (slot = ss & 1)
        #pragma unroll
        for (int ss = 0; ss < 8; ss++) {
            int s = s0 + ss;
            uint4 fa = *(const uint4*)&K[(g + 16*s    )*KP + 4*q];
            uint4 fb = *(const uint4*)&K[(g + 16*s + 8)*KP + 4*q];
            uint32_t da[2][2], db[2][2];
            #pragma unroll
            for (int mt = 0; mt < 2; mt++) {
                da[mt][0] = da[mt][1] = 0u;
                db[mt][0] = db[mt][1] = 0u;
                mma_f16d(da[mt], A[mt][0], fa.x, fa.y);
                mma_f16d(da[mt], A[mt][1], fa.z, fa.w);
                mma_f16d(db[mt], A[mt][0], fb.x, fb.y);
                mma_f16d(db[mt], A[mt][1], fb.z, fb.w);
            }
            if (ss >= 2) {   // GEMM2 for ss-2 (A2 long since ready)
                int sp = s - 2;
                uint32_t* A2 = &A2p[ss & 1][0][0];
                #pragma unroll
                for (int cf = 0; cf < 4; cf++) {
                    uint2 vv = *(const uint2*)&V[(g + 8*cf)*VP + 8*sp + 2*q];
                    #pragma unroll
                    for (int mt = 0; mt < 2; mt++)
                        mma_f16(mc[mt][cf], A2 + mt*4, vv.x, vv.y);
                }
            }
            #pragma unroll
            for (int mt = 0; mt < 2; mt++) {
                A2p[ss & 1][mt][0] = ex2h2(da[mt][0]);
                A2p[ss & 1][mt][1] = ex2h2(da[mt][1]);
                A2p[ss & 1][mt][2] = ex2h2(db[mt][0]);
                A2p[ss & 1][mt][3] = ex2h2(db[mt][1]);
            }
        }
        // flush GEMM2 for ss=6 (slot 0) and ss=7 (slot 1)
        #pragma unroll
        for (int fl = 0; fl < 2; fl++) {
            int sp = s0 + 6 + fl;
            uint32_t* A2 = &A2p[fl][0][0];
            #pragma unroll
            for (int cf = 0; cf < 4; cf++) {
                uint2 vv = *(const uint2*)&V[(g + 8*cf)*VP + 8*sp + 2*q];
                #pragma unroll
                for (int mt = 0; mt < 2; mt++)
                    mma_f16(mc[mt][cf], A2 + mt*4, vv.x, vv.y);
            }
        }
        __syncthreads();
    }

    // combine warp-pair partials via smem (reuse SH as msgP[256][MP])
    float* msgP = (float*)SH;
    if (wh == 1) {
        #pragma unroll
        for (int mt = 0; mt < 2; mt++) {
            int rb = wp*32 + mt*16;
            #pragma unroll
            for (int cf = 0; cf < 4; cf++) {
                int col = cf*8 + 2*q;
                *(float2*)&msgP[(rb + g    )*MP + col] =
                    make_float2(mc[mt][cf][0], mc[mt][cf][1]);
                *(float2*)&msgP[(rb + g + 8)*MP + col] =
                    make_float2(mc[mt][cf][2], mc[mt][cf][3]);
            }
        }
    }
    __syncthreads();

    if (wh == 0) {
        #pragma unroll
        for (int mt = 0; mt < 2; mt++) {
            int rb = wp*32 + mt*16;
            #pragma unroll
            for (int cf = 0; cf < 4; cf++) {
                int col = cf*8 + 2*q;
                float2 p0 = *(const float2*)&msgP[(rb + g    )*MP + col];
                float2 p1 = *(const float2*)&msgP[(rb + g + 8)*MP + col];
                mc[mt][cf][0] += p0.x; mc[mt][cf][1] += p0.y;
                mc[mt][cf][2] += p1.x; mc[mt][cf][3] += p1.y;
            }
        }
        #pragma unroll
        for (int mt = 0; mt < 2; mt++) {
            uint32_t A3[2][4];
            #pragma unroll
            for (int t = 0; t < 2; t++) {
                A3[t][0] = pk_h2(mc[mt][2*t  ][1], mc[mt][2*t  ][0]);
                A3[t][1] = pk_h2(mc[mt][2*t  ][3], mc[mt][2*t  ][2]);
                A3[t][2] = pk_h2(mc[mt][2*t+1][1], mc[mt][2*t+1][0]);
                A3[t][3] = pk_h2(mc[mt][2*t+1][3], mc[mt][2*t+1][2]);
            }
            long nbase = (long)b*N_ + n0 + wp*32 + mt*16;
            const float* gp = graph + nbase*32;
            float* op = out + nbase*32;
            #pragma unroll
            for (int of = 0; of < 4; of++) {
                int col = 8*of + 2*q;
                float bc0 = bc[col], bc1 = bc[col + 1];
                float2 gr0 = *(const float2*)(gp + g*32 + col);
                float2 gr1 = *(const float2*)(gp + (g + 8)*32 + col);
                float c[4] = { gr0.x + bc0, gr0.y + bc1, gr1.x + bc0, gr1.y + bc1 };
                #pragma unroll
                for (int t = 0; t < 2; t++) {
                    uint32_t b0 = Wb[(g + 8*of)*17 + 8*t + q    ];
                    uint32_t b1 = Wb[(g + 8*of)*17 + 8*t + q + 4];
                    mma_f16(c, A3[t], b0, b1);
                }
                *(float2*)(op + g*32 + col)       = make_float2(c[0], c[1]);
                *(float2*)(op + (g + 8)*32 + col) = make_float2(c[2], c[3]);
            }
        }
    }
}

// ===========================================================================
extern "C" void kernel_launch(void* const* d_in, const int* in_sizes, int n_in,
                              void* d_out, int out_size)
{
    const float* graph = (const float*)d_in[0];
    const float* img   = (const float*)d_in[1];
    const float* Wq    = (const float*)d_in[2];
    const float* bq    = (const float*)d_in[3];
    const float* Wk    = (const float*)d_in[4];
    const float* bk    = (const float*)d_in[5];
    const float* Wv    = (const float*)d_in[6];
    const float* bv    = (const float*)d_in[7];
    const float* Wc    = (const float*)d_in[8];
    const float* bc    = (const float*)d_in[9];
    float* out = (float*)d_out;

    size_t proj_smem = (64*PW + 2*64*PI) * sizeof(uint32_t);
    size_t fin_smem  = FN_WORDS * sizeof(uint32_t);
    static int attr_set = 0;
    if (!attr_set) {
        cudaFuncSetAttribute(k_proj_kv_mma,
                             cudaFuncAttributeMaxDynamicSharedMemorySize,
                             (int)proj_smem);
        cudaFuncSetAttribute(k_final_mma,
                             cudaFuncAttributeMaxDynamicSharedMemorySize,
                             (int)fin_smem);
        attr_set = 1;
    }

    k_proj_q     <<<B_*(N_/64), 256>>>(graph, Wq, bq);
    k_proj_kv_mma<<<B_*(L_/256), 256, proj_smem>>>(img, Wk, bk, Wv, bv);
    k_stats_mma  <<<B_*(L_/256), 512>>>();
    k_final_mma  <<<B_*(N_/256), 512, fin_smem>>>(graph, Wc, bc, out);
}

// round 17
// speedup vs baseline: 1.4080x; 1.0261x over previous
#include <cuda_runtime.h>
#include <cstdint>

#define B_  8
#define N_  4096
#define L_  4096
#define GC_ 32
#define IC_ 256

// K/Q rows stored in fragment order: word w -> perm16(w) = ((w&3)<<2)|(w>>2)
// V' pairs stored with in-block perm: j -> ((j&3)<<1)|((j>>2)&1)
__device__ uint32_t g_Qb [B_*N_*16];      // [b][n][w'] f16x2 (Q*QSCALE)
__device__ uint32_t g_Kb [B_*L_*16];      // [b][l][w'] f16x2
__device__ float    g_VTc[B_*GC_*L_];     // [b][c][l] raw f32 (channel-major)
__device__ uint32_t g_Vb [B_*GC_*(L_/2)]; // [b][c][l2'] f16x2 of V*Dinv

#define QSCALE 0.2550668292560464f  // (1/sqrt(32)) * log2(e)

// ===========================================================================
// helpers
// ===========================================================================
__device__ __forceinline__ uint32_t smem_u32(const void* p) {
    uint32_t a;
    asm("{ .reg .u64 t; cvta.to.shared.u64 t, %1; cvt.u32.u64 %0, t; }"
        : "=r"(a) : "l"(p));
    return a;
}
__device__ __forceinline__ uint32_t pk_h2(float hi, float lo) {
    uint32_t r;
    asm("cvt.rn.f16x2.f32 %0, %1, %2;" : "=r"(r) : "f"(hi), "f"(lo));
    return r;
}
__device__ __forceinline__ uint32_t ex2h2(uint32_t x) {
    uint32_t y;
    asm("ex2.approx.f16x2 %0, %1;" : "=r"(y) : "r"(x));
    return y;
}
__device__ __forceinline__ uint32_t hadd2(uint32_t a, uint32_t b) {
    uint32_t r;
    asm("add.rn.f16x2 %0, %1, %2;" : "=r"(r) : "r"(a), "r"(b));
    return r;
}
__device__ __forceinline__ float hsum2f(uint32_t h2) {
    float lo, hi;
    asm("{ .reg .b16 l, h;\n\t mov.b32 {l, h}, %2;\n\t"
        "cvt.f32.f16 %0, l;\n\t cvt.f32.f16 %1, h; }"
        : "=f"(lo), "=f"(hi) : "r"(h2));
    return lo + hi;
}
// f32-accumulate MMA
__device__ __forceinline__ void mma_f16(float c[4], const uint32_t a[4],
                                        uint32_t b0, uint32_t b1) {
    asm volatile("mma.sync.aligned.m16n8k16.row.col.f32.f16.f16.f32 "
        "{%0,%1,%2,%3}, {%4,%5,%6,%7}, {%8,%9}, {%0,%1,%2,%3};"
        : "+f"(c[0]), "+f"(c[1]), "+f"(c[2]), "+f"(c[3])
        : "r"(a[0]), "r"(a[1]), "r"(a[2]), "r"(a[3]), "r"(b0), "r"(b1));
}
// f16-accumulate MMA: D packs {row g: (2q, 2q+1)} in d[0], {row g+8: ...} in d[1]
__device__ __forceinline__ void mma_f16d(uint32_t d[2], const uint32_t a[4],
                                         uint32_t b0, uint32_t b1) {
    asm volatile("mma.sync.aligned.m16n8k16.row.col.f16.f16.f16.f16 "
        "{%0,%1}, {%2,%3,%4,%5}, {%6,%7}, {%0,%1};"
        : "+r"(d[0]), "+r"(d[1])
        : "r"(a[0]), "r"(a[1]), "r"(a[2]), "r"(a[3]), "r"(b0), "r"(b1));
}
__device__ __forceinline__ void cp16(uint32_t s, const void* g) {
    asm volatile("cp.async.ca.shared.global [%0], [%1], 16;"
                 :: "r"(s), "l"(g) : "memory");
}
#define CP_COMMIT() asm volatile("cp.async.commit_group;" ::: "memory")
#define CP_WAIT1()  asm volatile("cp.async.wait_group 1;" ::: "memory")
#define CP_WAIT0()  asm volatile("cp.async.wait_group 0;" ::: "memory")

// ===========================================================================
// Kernel 1: K/V projection via f16 MMA + fused Q projection tail.
// K stored fragment-order; V channel-major f32; Q packed f16x2 frag-order.
// grid = B*16 = 128 (each CTA: 256 l of K/V + 256 n of Q).
// ===========================================================================
#define PW 132
#define PI 260

__global__ __launch_bounds__(256, 1) void k_proj_kv_mma(
    const float* __restrict__ img,
    const float* __restrict__ Wk, const float* __restrict__ bk,
    const float* __restrict__ Wv, const float* __restrict__ bv,
    const float* __restrict__ graph, const float* __restrict__ Wq,
    const float* __restrict__ bq)
{
    extern __shared__ uint32_t shm[];
    uint32_t* Wsm  = shm;
    float*    img0 = (float*)(shm + 64*PW);
    float*    img1 = img0 + 64*PI;

    int tid = threadIdx.x, w = tid >> 5, lane = tid & 31;
    int q = lane & 3, g = lane >> 2;
    int b = blockIdx.x >> 4, l0 = (blockIdx.x & 15) * 256;

    #pragma unroll
    for (int t = 0; t < 32; t++) {
        int u = tid + t*256;
        int o = u >> 7, c2 = u & 127;
        const float* src = (o < 32) ? (Wk + o*IC_ + 2*c2) : (Wv + (o-32)*IC_ + 2*c2);
        float2 v = *(const float2*)src;
        Wsm[o*PW + c2] = pk_h2(v.y, v.x);
    }

    auto pref = [&](int ks, float* dstbuf) {
        const float* src = img + ((long)b*IC_ + ks*64)*L_ + l0;
        uint32_t dstb = smem_u32(dstbuf);
        #pragma unroll
        for (int t = 0; t < 16; t++) {
            int u = tid + t*256;
            int c = u >> 6, col = (u & 63) * 4;
            cp16(dstb + (c*PI + col)*4, src + (long)c*L_ + col);
        }
        CP_COMMIT();
    };
    pref(0, img0);

    float C[4][4][4];
    #pragma unroll
    for (int mt = 0; mt < 4; mt++) {
        const float* bias = (mt < 2) ? bk : bv;
        int ob = (mt & 1) * 16;
        float blo = bias[ob + g], bhi = bias[ob + 8 + g];
        #pragma unroll
        for (int nt = 0; nt < 4; nt++) {
            C[mt][nt][0] = C[mt][nt][1] = blo;
            C[mt][nt][2] = C[mt][nt][3] = bhi;
        }
    }
    __syncthreads();

    int lw = w * 32;
    for (int ks = 0; ks < 4; ks++) {
        if (ks < 3) { pref(ks + 1, (ks & 1) ? img0 : img1); CP_WAIT1(); }
        else CP_WAIT0();
        __syncthreads();
        const float* I = (ks & 1) ? img1 : img0;
        #pragma unroll
        for (int kk = 0; kk < 4; kk++) {
            uint32_t A[4][4];
            #pragma unroll
            for (int mt = 0; mt < 4; mt++) {
                const uint32_t* wp = Wsm + (mt*16)*PW + ks*32 + kk*8;
                A[mt][0] = wp[ g   *PW + q];
                A[mt][1] = wp[(g+8)*PW + q];
                A[mt][2] = wp[ g   *PW + q + 4];
                A[mt][3] = wp[(g+8)*PW + q + 4];
            }
            uint32_t Bf[4][2];
            #pragma unroll
            for (int nt = 0; nt < 4; nt++) {
                int l = lw + nt*8 + g;
                const float* r0 = I + (kk*16 + 2*q    )*PI + l;
                const float* r1 = I + (kk*16 + 2*q + 8)*PI + l;
                Bf[nt][0] = pk_h2(r0[PI], r0[0]);
                Bf[nt][1] = pk_h2(r1[PI], r1[0]);
            }
            #pragma unroll
            for (int mt = 0; mt < 4; mt++)
                #pragma unroll
                for (int nt = 0; nt < 4; nt++)
                    mma_f16(C[mt][nt], A[mt], Bf[nt][0], Bf[nt][1]);
        }
        __syncthreads();
    }

    // K epilogue: quad shfl-transpose -> g_Kb[l][w'] (fragment-order)
    bool odd = (g & 1);
    int sA = 8*q + (g >> 1), sB = sA + 4;
    #pragma unroll
    for (int mt = 0; mt < 2; mt++)
        #pragma unroll
        for (int nt = 0; nt < 4; nt++) {
            float* c = C[mt][nt];
            float t0 = __shfl_sync(~0u, c[0], sA), t1 = __shfl_sync(~0u, c[1], sA);
            float t2 = __shfl_sync(~0u, c[0], sB), t3 = __shfl_sync(~0u, c[1], sB);
            float t4 = __shfl_sync(~0u, c[2], sA), t5 = __shfl_sync(~0u, c[3], sA);
            float t6 = __shfl_sync(~0u, c[2], sB), t7 = __shfl_sync(~0u, c[3], sB);
            float lo0 = odd ? t1 : t0, hi0 = odd ? t3 : t2;
            float lo1 = odd ? t5 : t4, hi1 = odd ? t7 : t6;
            long l = (long)b*L_ + l0 + lw + nt*8 + g;
            g_Kb[l*16 + 4*q + 2*mt    ] = pk_h2(hi0, lo0);
            g_Kb[l*16 + 4*q + 2*mt + 1] = pk_h2(hi1, lo1);
        }
    #pragma unroll
    for (int mt = 2; mt < 4; mt++)
        #pragma unroll
        for (int nt = 0; nt < 4; nt++) {
            int c = (mt - 2)*16 + g;
            long base = ((long)b*GC_ + c)*L_ + l0 + lw + nt*8 + 2*q;
            *(float2*)(g_VTc + base)         = make_float2(C[mt][nt][0], C[mt][nt][1]);
            *(float2*)(g_VTc + base + 8*L_)  = make_float2(C[mt][nt][2], C[mt][nt][3]);
        }

    // ---- fused Q projection tail: 256 rows (same b / chunk mapping) ----
    __syncthreads();
    float* WqS = (float*)shm;            // pitch 33, 32 rows (fits in Wsm area)
    float* gS  = (float*)(shm + 64*PW);  // pitch 33, 256 rows (fits in img area)
    for (int i = tid; i < 32*32; i += 256)
        WqS[(i >> 5)*33 + (i & 31)] = Wq[i];
    int nq0 = (blockIdx.x & 15) * 256;
    const float* gp = graph + ((long)b*N_ + nq0)*GC_;
    for (int i = tid; i < 256*32; i += 256)
        gS[(i >> 5)*33 + (i & 31)] = gp[i];
    __syncthreads();

    int o2 = tid & 15, nb = tid >> 4;
    int po2 = ((o2 & 3) << 2) | (o2 >> 2);   // perm16
    float qb0 = bq[2*o2], qb1 = bq[2*o2 + 1];
    #pragma unroll
    for (int j = 0; j < 16; j++) {
        int n = nb + 16*j;
        float a0 = qb0, a1 = qb1;
        #pragma unroll
        for (int c = 0; c < 32; c++) {
            float gv = gS[n*33 + c];
            a0 += WqS[(2*o2    )*33 + c] * gv;
            a1 += WqS[(2*o2 + 1)*33 + c] * gv;
        }
        g_Qb[((long)b*N_ + nq0 + n)*16 + po2] = pk_h2(a1*QSCALE, a0*QSCALE);
    }
}

// ===========================================================================
// Kernel 2: stats, 512 threads, 256-n tiles. f16-acc GEMM1 feeds ex2h2
// directly; exp/accumulate of step jj-1 overlaps MMAs of jj (1-stage pipe).
// ===========================================================================
__global__ __launch_bounds__(512, 1) void k_stats_mma()
{
    __shared__ __align__(16) uint32_t Qs[2][256*16];
    __shared__ float dS[2][256];
    __shared__ float dinvS[256];
    int tid = threadIdx.x, w = tid >> 5, lane = tid & 31;
    int wp = w & 7, wh = w >> 3;
    int q = lane & 3, g = lane >> 2;
    int b = blockIdx.x >> 4, l0 = (blockIdx.x & 15) * 256;
    uint32_t qs_b = smem_u32(Qs);

    uint32_t A[2][2][4];
    #pragma unroll
    for (int mt = 0; mt < 2; mt++) {
        const uint32_t* kp = g_Kb + ((long)b*L_ + l0 + wp*32 + mt*16)*16;
        #pragma unroll
        for (int kk = 0; kk < 2; kk++) {
            A[mt][kk][0] = kp[ g   *16 + 4*q + 2*kk    ];
            A[mt][kk][1] = kp[(g+8)*16 + 4*q + 2*kk    ];
            A[mt][kk][2] = kp[ g   *16 + 4*q + 2*kk + 1];
            A[mt][kk][3] = kp[(g+8)*16 + 4*q + 2*kk + 1];
        }
    }

    auto prefetch = [&](int nc, int buf) {
        const uint32_t* src = g_Qb + ((long)b*N_ + nc*256)*16;
        #pragma unroll
        for (int it = 0; it < 2; it++) {
            int u = tid + it*512;
            int r = u >> 2, t = u & 3;
            cp16(qs_b + (buf*256*16 + r*16 + 4*t)*4, src + r*16 + 4*t);
        }
        CP_COMMIT();
    };
    prefetch(0, 0);

    float d[2][2] = {{0.f,0.f},{0.f,0.f}};
    int j0 = wh * 16;
    for (int nc = 0; nc < 16; nc++) {
        if (nc < 15) { prefetch(nc + 1, (nc + 1) & 1); CP_WAIT1(); }
        else CP_WAIT0();
        __syncthreads();
        const uint32_t* Q = &Qs[nc & 1][0];
        uint32_t dh[2][2] = {{0u,0u},{0u,0u}};
        uint32_t ddp[2][2];   // previous step's GEMM1 results
        #pragma unroll 4
        for (int jj = 0; jj < 16; jj++) {
            int j = j0 + jj;
            uint4 f = *(const uint4*)&Q[(g + 8*j)*16 + 4*q];
            uint32_t dd[2][2];
            #pragma unroll
            for (int mt = 0; mt < 2; mt++) {
                dd[mt][0] = dd[mt][1] = 0u;
                mma_f16d(dd[mt], A[mt][0], f.x, f.y);
                mma_f16d(dd[mt], A[mt][1], f.z, f.w);
            }
            if (jj > 0) {   // exp/accumulate previous step (overlaps MMAs above)
                #pragma unroll
                for (int mt = 0; mt < 2; mt++) {
                    dh[mt][0] = hadd2(dh[mt][0], ex2h2(ddp[mt][0]));
                    dh[mt][1] = hadd2(dh[mt][1], ex2h2(ddp[mt][1]));
                }
            }
            #pragma unroll
            for (int mt = 0; mt < 2; mt++) {
                ddp[mt][0] = dd[mt][0];
                ddp[mt][1] = dd[mt][1];
            }
        }
        #pragma unroll
        for (int mt = 0; mt < 2; mt++) {   // flush last step
            dh[mt][0] = hadd2(dh[mt][0], ex2h2(ddp[mt][0]));
            dh[mt][1] = hadd2(dh[mt][1], ex2h2(ddp[mt][1]));
            d[mt][0] += hsum2f(dh[mt][0]);
            d[mt][1] += hsum2f(dh[mt][1]);
        }
        __syncthreads();
    }
    #pragma unroll
    for (int mt = 0; mt < 2; mt++) {
        #pragma unroll
        for (int h = 0; h < 2; h++) {
            float dv = d[mt][h];
            dv += __shfl_xor_sync(~0u, dv, 1);
            dv += __shfl_xor_sync(~0u, dv, 2);
            if (q == 0) dS[wh][wp*32 + mt*16 + h*8 + g] = dv;
        }
    }
    __syncthreads();
    if (tid < 256) dinvS[tid] = 1.0f / (dS[0][tid] + dS[1][tid]);
    __syncthreads();

    // V' pack: destination index permuted within 8-word blocks
    uint32_t* dst = g_Vb + ((long)b*GC_)*(L_/2) + (l0 >> 1);
    const float* vsrc = g_VTc + ((long)b*GC_)*L_ + l0;
    #pragma unroll
    for (int t = 0; t < 8; t++) {
        int u = tid + t*512;
        int c = u >> 7, l2 = u & 127;
        int l2p = (l2 & ~7) | ((l2 & 3) << 1) | ((l2 >> 2) & 1);
        float2 v = *(const float2*)(vsrc + (long)c*L_ + 2*l2);
        dst[(long)c*(L_/2) + l2p] =
            pk_h2(v.y * dinvS[2*l2 + 1], v.x * dinvS[2*l2]);
    }
}

// ===========================================================================
// Kernel 3: final, 512 threads, 256-l tiles, dynamic smem.
// f16-acc GEMM1 -> ex2h2 on D regs; 1-stage exp pipeline
// (GEMM2(ss-1) overlaps GEMM1(ss)) — best measured variant (R15).
// ===========================================================================
#define KP 16
#define VP 136
#define VB_OFF (2*256*KP)
#define WB_OFF (VB_OFF + 2*32*VP)
#define FN_WORDS (WB_OFF + 32*17)
#define MP 34

__global__ __launch_bounds__(512, 1) void k_final_mma(
    const float* __restrict__ graph, const float* __restrict__ Wc,
    const float* __restrict__ bc, float* __restrict__ out)
{
    extern __shared__ __align__(16) uint32_t SH[];
    uint32_t* Wb = SH + WB_OFF;
    int tid = threadIdx.x, w = tid >> 5, lane = tid & 31;
    int wp = w & 7, wh = w >> 3;
    int q = lane & 3, g = lane >> 2;
    int b = blockIdx.x >> 4, n0 = (blockIdx.x & 15) * 256;
    uint32_t sh_b = smem_u32(SH);

    uint32_t A[2][2][4];
    #pragma unroll
    for (int mt = 0; mt < 2; mt++) {
        const uint32_t* qp = g_Qb + ((long)b*N_ + n0 + wp*32 + mt*16)*16;
        #pragma unroll
        for (int kk = 0; kk < 2; kk++) {
            A[mt][kk][0] = qp[ g   *16 + 4*q + 2*kk    ];
            A[mt][kk][1] = qp[(g+8)*16 + 4*q + 2*kk    ];
            A[mt][kk][2] = qp[ g   *16 + 4*q + 2*kk + 1];
            A[mt][kk][3] = qp[(g+8)*16 + 4*q + 2*kk + 1];
        }
    }
    for (int i = tid; i < 32*16; i += 512) {
        int o = i >> 4, c2 = i & 15;
        Wb[o*17 + c2] = pk_h2(Wc[o*32 + 2*c2 + 1], Wc[o*32 + 2*c2]);
    }

    const uint32_t* vbsrc = g_Vb + ((long)b*GC_)*(L_/2);
    auto prefetch = [&](int lc, int buf) {
        const uint32_t* ksrc = g_Kb + ((long)b*L_ + lc*256)*16;
        #pragma unroll
        for (int it = 0; it < 2; it++) {
            int u = tid + it*512;
            int r = u >> 2, t = u & 3;
            cp16(sh_b + (buf*256*KP + r*KP + 4*t)*4, ksrc + r*16 + 4*t);
        }
        #pragma unroll
        for (int it = 0; it < 2; it++) {
            int u = tid + it*512;
            int c = u >> 5, t2 = u & 31;
            cp16(sh_b + (VB_OFF + buf*32*VP + c*VP + 4*t2)*4,
                 vbsrc + (long)c*(L_/2) + lc*128 + 4*t2);
        }
        CP_COMMIT();
    };
    prefetch(0, 0);

    float mc[2][4][4];
    #pragma unroll
    for (int mt = 0; mt < 2; mt++)
        #pragma unroll
        for (int cf = 0; cf < 4; cf++)
            #pragma unroll
            for (int x = 0; x < 4; x++) mc[mt][cf][x] = 0.f;

    int s0 = wh * 8;
    for (int lc = 0; lc < 16; lc++) {
        if (lc < 15) { prefetch(lc + 1, (lc + 1) & 1); CP_WAIT1(); }
        else CP_WAIT0();
        __syncthreads();
        const uint32_t* K = SH + (lc & 1)*256*KP;
        const uint32_t* V = SH + VB_OFF + (lc & 1)*32*VP;

        uint32_t A2p[2][4];   // exp fragments of previous ss
        #pragma unroll
        for (int ss = 0; ss < 8; ss++) {
            int s = s0 + ss;
            uint4 fa = *(const uint4*)&K[(g + 16*s    )*KP + 4*q];
            uint4 fb = *(const uint4*)&K[(g + 16*s + 8)*KP + 4*q];
            uint32_t da[2][2], db[2][2];
            #pragma unroll
            for (int mt = 0; mt < 2; mt++) {
                da[mt][0] = da[mt][1] = 0u;
                db[mt][0] = db[mt][1] = 0u;
                mma_f16d(da[mt], A[mt][0], fa.x, fa.y);
                mma_f16d(da[mt], A[mt][1], fa.z, fa.w);
                mma_f16d(db[mt], A[mt][0], fb.x, fb.y);
                mma_f16d(db[mt], A[mt][1], fb.z, fb.w);
            }
            if (ss > 0) {   // GEMM2 for previous ss (A2p ready)
                int sp = s - 1;
                #pragma unroll
                for (int cf = 0; cf < 4; cf++) {
                    uint2 vv = *(const uint2*)&V[(g + 8*cf)*VP + 8*sp + 2*q];
                    #pragma unroll
                    for (int mt = 0; mt < 2; mt++)
                        mma_f16(mc[mt][cf], A2p[mt], vv.x, vv.y);
                }
            }
            #pragma unroll
            for (int mt = 0; mt < 2; mt++) {
                A2p[mt][0] = ex2h2(da[mt][0]);
                A2p[mt][1] = ex2h2(da[mt][1]);
                A2p[mt][2] = ex2h2(db[mt][0]);
                A2p[mt][3] = ex2h2(db[mt][1]);
            }
        }
        {   // flush GEMM2 for last ss of this lc
            int sp = s0 + 7;
            #pragma unroll
            for (int cf = 0; cf < 4; cf++) {
                uint2 vv = *(const uint2*)&V[(g + 8*cf)*VP + 8*sp + 2*q];
                #pragma unroll
                for (int mt = 0; mt < 2; mt++)
                    mma_f16(mc[mt][cf], A2p[mt], vv.x, vv.y);
            }
        }
        __syncthreads();
    }

    // combine warp-pair partials via smem (reuse SH as msgP[256][MP])
    float* msgP = (float*)SH;
    if (wh == 1) {
        #pragma unroll
        for (int mt = 0; mt < 2; mt++) {
            int rb = wp*32 + mt*16;
            #pragma unroll
            for (int cf = 0; cf < 4; cf++) {
                int col = cf*8 + 2*q;
                *(float2*)&msgP[(rb + g    )*MP + col] =
                    make_float2(mc[mt][cf][0], mc[mt][cf][1]);
                *(float2*)&msgP[(rb + g + 8)*MP + col] =
                    make_float2(mc[mt][cf][2], mc[mt][cf][3]);
            }
        }
    }
    __syncthreads();

    if (wh == 0) {
        #pragma unroll
        for (int mt = 0; mt < 2; mt++) {
            int rb = wp*32 + mt*16;
            #pragma unroll
            for (int cf = 0; cf < 4; cf++) {
                int col = cf*8 + 2*q;
                float2 p0 = *(const float2*)&msgP[(rb + g    )*MP + col];
                float2 p1 = *(const float2*)&msgP[(rb + g + 8)*MP + col];
                mc[mt][cf][0] += p0.x; mc[mt][cf][1] += p0.y;
                mc[mt][cf][2] += p1.x; mc[mt][cf][3] += p1.y;
            }
        }
        #pragma unroll
        for (int mt = 0; mt < 2; mt++) {
            uint32_t A3[2][4];
            #pragma unroll
            for (int t = 0; t < 2; t++) {
                A3[t][0] = pk_h2(mc[mt][2*t  ][1], mc[mt][2*t  ][0]);
                A3[t][1] = pk_h2(mc[mt][2*t  ][3], mc[mt][2*t  ][2]);
                A3[t][2] = pk_h2(mc[mt][2*t+1][1], mc[mt][2*t+1][0]);
                A3[t][3] = pk_h2(mc[mt][2*t+1][3], mc[mt][2*t+1][2]);
            }
            long nbase = (long)b*N_ + n0 + wp*32 + mt*16;
            const float* gp = graph + nbase*32;
            float* op = out + nbase*32;
            #pragma unroll
            for (int of = 0; of < 4; of++) {
                int col = 8*of + 2*q;
                float bc0 = bc[col], bc1 = bc[col + 1];
                float2 gr0 = *(const float2*)(gp + g*32 + col);
                float2 gr1 = *(const float2*)(gp + (g + 8)*32 + col);
                float c[4] = { gr0.x + bc0, gr0.y + bc1, gr1.x + bc0, gr1.y + bc1 };
                #pragma unroll
                for (int t = 0; t < 2; t++) {
                    uint32_t b0 = Wb[(g + 8*of)*17 + 8*t + q    ];
                    uint32_t b1 = Wb[(g + 8*of)*17 + 8*t + q + 4];
                    mma_f16(c, A3[t], b0, b1);
                }
                *(float2*)(op + g*32 + col)       = make_float2(c[0], c[1]);
                *(float2*)(op + (g + 8)*32 + col) = make_float2(c[2], c[3]);
            }
        }
    }
}

// ===========================================================================
extern "C" void kernel_launch(void* const* d_in, const int* in_sizes, int n_in,
                              void* d_out, int out_size)
{
    const float* graph = (const float*)d_in[0];
    const float* img   = (const float*)d_in[1];
    const float* Wq    = (const float*)d_in[2];
    const float* bq    = (const float*)d_in[3];
    const float* Wk    = (const float*)d_in[4];
    const float* bk    = (const float*)d_in[5];
    const float* Wv    = (const float*)d_in[6];
    const float* bv    = (const float*)d_in[7];
    const float* Wc    = (const float*)d_in[8];
    const float* bc    = (const float*)d_in[9];
    float* out = (float*)d_out;

    size_t proj_smem = (64*PW + 2*64*PI) * sizeof(uint32_t);
    size_t fin_smem  = FN_WORDS * sizeof(uint32_t);
    static int attr_set = 0;
    if (!attr_set) {
        cudaFuncSetAttribute(k_proj_kv_mma,
                             cudaFuncAttributeMaxDynamicSharedMemorySize,
                             (int)proj_smem);
        cudaFuncSetAttribute(k_final_mma,
                             cudaFuncAttributeMaxDynamicSharedMemorySize,
                             (int)fin_smem);
        attr_set = 1;
    }

    k_proj_kv_mma<<<B_*(L_/256), 256, proj_smem>>>(img, Wk, bk, Wv, bv,
                                                   graph, Wq, bq);
    k_stats_mma  <<<B_*(L_/256), 512>>>();
    k_final_mma  <<<B_*(N_/256), 512, fin_smem>>>(graph, Wc, bc, out);
}